// round 12
// baseline (speedup 1.0000x reference)
#include <cuda_runtime.h>

typedef unsigned long long ull;

__device__ __forceinline__ ull pk(float lo, float hi) {
    ull r; asm("mov.b64 %0,{%1,%2};" : "=l"(r) : "f"(lo), "f"(hi)); return r;
}
__device__ __forceinline__ void upk(ull v, float& lo, float& hi) {
    asm("mov.b64 {%0,%1},%2;" : "=f"(lo), "=f"(hi) : "l"(v));
}
__device__ __forceinline__ void ffma2(ull& d, ull a, ull b) {
    asm("fma.rn.f32x2 %0,%1,%2,%0;" : "+l"(d) : "l"(a), "l"(b));
}

// ---------------- constants ----------------
constexpr int F  = 114176;
constexpr int F2 = 114688;
constexpr int OW0 = 0, OB0 = 1728, OW1 = 1792, OB1 = 38656, OW2 = 38720,
              OB2 = 75584, OW3 = 75648, OB3 = 112512, OFC = 112576;
constexpr int WTS = 64*64*9;

// ---------------- scratch ----------------
__device__ float g_x  [128*3*84*84];
__device__ float g_p0 [128*64*42*42];
__device__ float g_dp0[128*64*42*42];
__device__ unsigned char g_i0[128*64*42*42];
__device__ float g_p1 [128*64*21*21];
__device__ float g_dp1[128*64*21*21];
__device__ unsigned char g_i1[128*64*21*21];
__device__ float g_p2 [128*64*10*10];
__device__ float g_d3 [128*64*10*10];
__device__ float g_dp2[128*64*10*10];
__device__ unsigned char g_i2[128*64*10*10];
__device__ float g_p3 [128*64*5*5];
__device__ unsigned char g_i3[128*64*5*5];
__device__ float g_wt [3*WTS];
__device__ float g_G  [128*(size_t)F2];
__device__ float g_part[128*4096];

// ---------------- kernels ----------------
__global__ void pack_x_k(const float* __restrict__ x1, const float* __restrict__ x2,
                         float* __restrict__ xo) {
    int t = blockIdx.x*256 + threadIdx.x;
    const int P = 3*84*84;
    if (t >= 128*P) return;
    int n = t / P, k = t - n*P;
    xo[t] = (n < 64) ? x1[n*P + k] : x2[(n-64)*P + k];
}

__global__ void zpad_k(float* __restrict__ G) {
    int t = blockIdx.x*256 + threadIdx.x;
    if (t >= 128*(F2-F)) return;
    int n = t >> 9, j = t & 511;
    G[(size_t)n*F2 + F + j] = 0.f;
}

// fused conv3x3(SAME)+bias+relu+2x2 maxpool; 8 oc x 4 px register tiles (scalar)
template<int IC, int NPB, int PXT, bool VEC>
__launch_bounds__(128)
__global__ void convpool_k(const float* __restrict__ in, const float* __restrict__ w,
                           const float* __restrict__ bias, float* __restrict__ p,
                           unsigned char* __restrict__ idx,
                           int H, int W, int Hp, int Wp)
{
    const int oc0 = blockIdx.y*8;
    __shared__ float ws[8*IC*12];
    __shared__ float bs[8];
    for (int i = threadIdx.x; i < 8*IC*9; i += 128) {
        int oi = i/9, k = i - oi*9;
        ws[oi*12+k] = w[(size_t)oc0*IC*9 + i];
    }
    if (threadIdx.x < 8) bs[threadIdx.x] = bias[oc0+threadIdx.x];
    __syncthreads();
    int n, t;
    if (NPB == 1) {
        n = blockIdx.z; t = blockIdx.x*128 + threadIdx.x;
        if (t >= Hp*Wp) return;
    } else {
        int q = threadIdx.x / PXT; t = threadIdx.x - q*PXT;
        n = blockIdx.z*NPB + q;
        if (q >= NPB || n >= 128) return;
    }
    int py = t / Wp, px = t - py*Wp;
    int y0 = py*2, x0 = px*2;
    bool rv[4];
    #pragma unroll
    for (int u = 0; u < 4; u++) { int yy = y0-1+u; rv[u] = (unsigned)yy < (unsigned)H; }
    const bool ax = (x0 >= 2);
    const bool cx = (x0 + 2 < W);
    int offs[4][4];
    if (!VEC) {
        #pragma unroll
        for (int u = 0; u < 4; u++)
        #pragma unroll
        for (int j = 0; j < 4; j++) {
            int xx = x0-1+j;
            offs[u][j] = (rv[u] && (unsigned)xx < (unsigned)W) ? (y0-1+u)*W+xx : -1;
        }
    }
    float acc[8][4];
    #pragma unroll
    for (int o = 0; o < 8; o++) {
        float b = bs[o];
        acc[o][0]=b; acc[o][1]=b; acc[o][2]=b; acc[o][3]=b;
    }
    const int HW = H*W;
    const float* ip = in + (size_t)n*IC*HW;
    const float* bp = ip + (y0-1)*W + x0;
    #pragma unroll 1
    for (int ic = 0; ic < IC; ic++, ip += HW, bp += HW) {
        float v[4][4];
        if (VEC) {
            #pragma unroll
            for (int u = 0; u < 4; u++) {
                const float* rp = bp + u*W;
                float2 A = (rv[u] && ax) ? *(const float2*)(rp - 2) : make_float2(0.f, 0.f);
                float2 B =  rv[u]        ? *(const float2*)(rp    ) : make_float2(0.f, 0.f);
                float2 C = (rv[u] && cx) ? *(const float2*)(rp + 2) : make_float2(0.f, 0.f);
                v[u][0] = A.y; v[u][1] = B.x; v[u][2] = B.y; v[u][3] = C.x;
            }
        } else {
            #pragma unroll
            for (int u = 0; u < 4; u++)
            #pragma unroll
            for (int j = 0; j < 4; j++)
                v[u][j] = (offs[u][j] >= 0) ? ip[offs[u][j]] : 0.0f;
        }
        #pragma unroll
        for (int o = 0; o < 8; o++) {
            float wr[12];
            *(float4*)&wr[0] = *(const float4*)&ws[(o*IC+ic)*12];
            *(float4*)&wr[4] = *(const float4*)&ws[(o*IC+ic)*12+4];
            wr[8] = ws[(o*IC+ic)*12+8];
            #pragma unroll
            for (int u = 0; u < 3; u++)
            #pragma unroll
            for (int vv = 0; vv < 3; vv++) {
                float wv = wr[u*3+vv];
                acc[o][0] += wv*v[u  ][vv  ];
                acc[o][1] += wv*v[u  ][vv+1];
                acc[o][2] += wv*v[u+1][vv  ];
                acc[o][3] += wv*v[u+1][vv+1];
            }
        }
    }
    #pragma unroll
    for (int o = 0; o < 8; o++) {
        float a0 = fmaxf(acc[o][0],0.f), a1 = fmaxf(acc[o][1],0.f),
              a2 = fmaxf(acc[o][2],0.f), a3 = fmaxf(acc[o][3],0.f);
        float m = a0; int am = 0;
        if (a1 > m) { m = a1; am = 1; }
        if (a2 > m) { m = a2; am = 2; }
        if (a3 > m) { m = a3; am = 3; }
        size_t ob = ((size_t)(n*64+oc0+o)*Hp + py)*Wp + px;
        p[ob] = m;
        idx[ob] = (m > 0.f) ? (unsigned char)am : (unsigned char)4;
    }
}

// PACKED f32x2 fused conv+bias+relu+pool, IC=64, W even (42x42 layer).
// acc0[o]=(px00,px01) top row of quad, acc1[o]=(px10,px11) bottom row.
__launch_bounds__(128)
__global__ void convpool8p_k(const float* __restrict__ in, const float* __restrict__ w,
                             const float* __restrict__ bias, float* __restrict__ p,
                             unsigned char* __restrict__ idx,
                             int H, int W, int Hp, int Wp)
{
    const int oc0 = blockIdx.y*8;
    __shared__ ull ws2[8*64*10];    // (w,w) pairs, 9 used + 1 pad -> 16B-aligned rows
    __shared__ float bs[8];
    for (int i = threadIdx.x; i < 8*64*9; i += 128) {
        int oi = i/9, k = i - oi*9;
        float wv = w[(size_t)oc0*64*9 + i];
        ws2[oi*10+k] = pk(wv, wv);
    }
    if (threadIdx.x < 8) bs[threadIdx.x] = bias[oc0+threadIdx.x];
    __syncthreads();
    const int n = blockIdx.z;
    int t = blockIdx.x*128 + threadIdx.x;
    if (t >= Hp*Wp) return;
    int py = t / Wp, px = t - py*Wp;
    int y0 = py*2, x0 = px*2;
    bool rv[4];
    #pragma unroll
    for (int u = 0; u < 4; u++) { int yy = y0-1+u; rv[u] = (unsigned)yy < (unsigned)H; }
    const bool ax = (x0 >= 2);
    const bool cx = (x0 + 2 < W);
    ull acc0[8], acc1[8];
    #pragma unroll
    for (int o = 0; o < 8; o++) { float b = bs[o]; acc0[o] = pk(b,b); acc1[o] = pk(b,b); }
    const int HW = H*W;
    const float* bp = in + (size_t)n*64*HW + (y0-1)*W + x0;
    #pragma unroll 1
    for (int ic = 0; ic < 64; ic++, bp += HW) {
        ull pr[4][3];
        #pragma unroll
        for (int u = 0; u < 4; u++) {
            const float* rp = bp + u*W;
            float2 A = (rv[u] && ax) ? *(const float2*)(rp - 2) : make_float2(0.f, 0.f);
            float2 B =  rv[u]        ? *(const float2*)(rp    ) : make_float2(0.f, 0.f);
            float2 C = (rv[u] && cx) ? *(const float2*)(rp + 2) : make_float2(0.f, 0.f);
            pr[u][0] = pk(A.y, B.x);
            pr[u][1] = pk(B.x, B.y);
            pr[u][2] = pk(B.y, C.x);
        }
        #pragma unroll
        for (int o = 0; o < 8; o++) {
            const ull* wp = &ws2[(o*64+ic)*10];
            ull wr[9];
            *(ulonglong2*)&wr[0] = *(const ulonglong2*)(wp+0);
            *(ulonglong2*)&wr[2] = *(const ulonglong2*)(wp+2);
            *(ulonglong2*)&wr[4] = *(const ulonglong2*)(wp+4);
            *(ulonglong2*)&wr[6] = *(const ulonglong2*)(wp+6);
            wr[8] = wp[8];
            #pragma unroll
            for (int u = 0; u < 3; u++)
            #pragma unroll
            for (int vv = 0; vv < 3; vv++) {
                ffma2(acc0[o], wr[u*3+vv], pr[u  ][vv]);
                ffma2(acc1[o], wr[u*3+vv], pr[u+1][vv]);
            }
        }
    }
    #pragma unroll
    for (int o = 0; o < 8; o++) {
        float a0,a1,a2,a3;
        upk(acc0[o], a0, a1); upk(acc1[o], a2, a3);
        a0 = fmaxf(a0,0.f); a1 = fmaxf(a1,0.f); a2 = fmaxf(a2,0.f); a3 = fmaxf(a3,0.f);
        float m = a0; int am = 0;
        if (a1 > m) { m = a1; am = 1; }
        if (a2 > m) { m = a2; am = 2; }
        if (a3 > m) { m = a3; am = 3; }
        size_t ob = ((size_t)(n*64+oc0+o)*Hp + py)*Wp + px;
        p[ob] = m;
        idx[ob] = (m > 0.f) ? (unsigned char)am : (unsigned char)4;
    }
}

// PACKED f32x2 backward-data conv with fused unpool (42x42 output layer)
__launch_bounds__(128)
__global__ void conv2f8p_k(const float* __restrict__ dp, const unsigned char* __restrict__ ib,
                           const float* __restrict__ w, float* __restrict__ out,
                           int H, int W, int Hp, int Wp)
{
    const int n = blockIdx.z, oc0 = blockIdx.y*8;
    const int TW = (W+1) >> 1, TH = (H+1) >> 1;
    __shared__ ull ws2[8*64*10];
    for (int i = threadIdx.x; i < 8*64*9; i += 128) {
        int oi = i/9, k = i - oi*9;
        float wv = w[(size_t)oc0*64*9 + i];
        ws2[oi*10+k] = pk(wv, wv);
    }
    __syncthreads();
    int t = blockIdx.x*128 + threadIdx.x;
    if (t >= TH*TW) return;
    int ty = t / TW, tx = t - ty*TW;
    int poff[3][3];
    #pragma unroll
    for (int a = 0; a < 3; a++) {
        int py = ty - 1 + a; bool rv = (unsigned)py < (unsigned)Hp;
        #pragma unroll
        for (int b = 0; b < 3; b++) {
            int px = tx - 1 + b;
            poff[a][b] = (rv && (unsigned)px < (unsigned)Wp) ? py*Wp+px : -1;
        }
    }
    const int AY[4] = {0,1,1,2};
    const int QY[4] = {1,0,1,0};
    ull acc0[8], acc1[8];
    #pragma unroll
    for (int o = 0; o < 8; o++) { acc0[o] = 0ull; acc1[o] = 0ull; }
    const int PS = Hp*Wp;
    const float* dpp = dp + (size_t)n*64*PS;
    const unsigned char* ibp = ib + (size_t)n*64*PS;
    #pragma unroll 1
    for (int ic = 0; ic < 64; ic++, dpp += PS, ibp += PS) {
        float d[3][3]; int id[3][3];
        #pragma unroll
        for (int a = 0; a < 3; a++)
        #pragma unroll
        for (int b = 0; b < 3; b++) {
            int o2 = poff[a][b];
            bool v2 = (o2 >= 0);
            d[a][b]  = v2 ? dpp[o2] : 0.f;
            id[a][b] = v2 ? (int)ibp[o2] : 4;
        }
        float v[4][4];
        #pragma unroll
        for (int u = 0; u < 4; u++)
        #pragma unroll
        for (int j = 0; j < 4; j++) {
            int a = AY[u], b = AY[j];
            int qq = QY[u]*2 + QY[j];
            v[u][j] = (id[a][b] == qq) ? d[a][b] : 0.f;
        }
        ull pr[4][3];
        #pragma unroll
        for (int u = 0; u < 4; u++) {
            pr[u][0] = pk(v[u][0], v[u][1]);
            pr[u][1] = pk(v[u][1], v[u][2]);
            pr[u][2] = pk(v[u][2], v[u][3]);
        }
        #pragma unroll
        for (int o = 0; o < 8; o++) {
            const ull* wp = &ws2[(o*64+ic)*10];
            ull wr[9];
            *(ulonglong2*)&wr[0] = *(const ulonglong2*)(wp+0);
            *(ulonglong2*)&wr[2] = *(const ulonglong2*)(wp+2);
            *(ulonglong2*)&wr[4] = *(const ulonglong2*)(wp+4);
            *(ulonglong2*)&wr[6] = *(const ulonglong2*)(wp+6);
            wr[8] = wp[8];
            #pragma unroll
            for (int u = 0; u < 3; u++)
            #pragma unroll
            for (int vv = 0; vv < 3; vv++) {
                ffma2(acc0[o], wr[u*3+vv], pr[u  ][vv]);
                ffma2(acc1[o], wr[u*3+vv], pr[u+1][vv]);
            }
        }
    }
    int y0 = 2*ty, x0 = 2*tx;
    bool xv = (x0+1 < W), yv = (y0+1 < H);
    #pragma unroll
    for (int o = 0; o < 8; o++) {
        float a0,a1,a2,a3;
        upk(acc0[o], a0, a1); upk(acc1[o], a2, a3);
        float* op = out + ((size_t)(n*64+oc0+o)*H + y0)*W + x0;
        op[0] = a0;
        if (xv) op[1] = a1;
        if (yv) { op[W] = a2; if (xv) op[W+1] = a3; }
    }
}

// plain backward-data conv (10x10 layer only), 8 oc
template<int IC, int NPB, int PXT>
__launch_bounds__(128)
__global__ void conv2_k(const float* __restrict__ in, const float* __restrict__ w,
                        float* __restrict__ out, int H, int W)
{
    const int n0 = blockIdx.z, oc0 = blockIdx.y*8;
    const int TW = (W+1) >> 1;
    __shared__ float ws[8*IC*12];
    for (int i = threadIdx.x; i < 8*IC*9; i += 128) {
        int oi = i/9, k = i - oi*9;
        ws[oi*12+k] = w[(size_t)oc0*IC*9 + i];
    }
    __syncthreads();
    int q = threadIdx.x / PXT, t = threadIdx.x - q*PXT;
    int n = n0*NPB + q;
    if (q >= NPB || n >= 128) return;
    int ty = t / TW, tx = t - ty*TW;
    int y0 = ty*2, x0 = tx*2;
    int offs[4][4];
    #pragma unroll
    for (int u = 0; u < 4; u++) {
        int yy = y0-1+u; bool rv = (unsigned)yy < (unsigned)H;
        #pragma unroll
        for (int j = 0; j < 4; j++) {
            int xx = x0-1+j;
            offs[u][j] = (rv && (unsigned)xx < (unsigned)W) ? yy*W+xx : -1;
        }
    }
    float acc[8][4];
    #pragma unroll
    for (int o = 0; o < 8; o++) { acc[o][0]=0.f; acc[o][1]=0.f; acc[o][2]=0.f; acc[o][3]=0.f; }
    const float* ip = in + (size_t)n*IC*H*W;
    #pragma unroll 1
    for (int ic = 0; ic < IC; ic++, ip += H*W) {
        float v[4][4];
        #pragma unroll
        for (int u = 0; u < 4; u++)
        #pragma unroll
        for (int j = 0; j < 4; j++)
            v[u][j] = (offs[u][j] >= 0) ? ip[offs[u][j]] : 0.0f;
        #pragma unroll
        for (int o = 0; o < 8; o++) {
            float wr[12];
            *(float4*)&wr[0] = *(const float4*)&ws[(o*IC+ic)*12];
            *(float4*)&wr[4] = *(const float4*)&ws[(o*IC+ic)*12+4];
            wr[8] = ws[(o*IC+ic)*12+8];
            #pragma unroll
            for (int u = 0; u < 3; u++)
            #pragma unroll
            for (int vv = 0; vv < 3; vv++) {
                float wv = wr[u*3+vv];
                acc[o][0] += wv*v[u  ][vv  ];
                acc[o][1] += wv*v[u  ][vv+1];
                acc[o][2] += wv*v[u+1][vv  ];
                acc[o][3] += wv*v[u+1][vv+1];
            }
        }
    }
    bool xv = (x0+1 < W), yv = (y0+1 < H);
    #pragma unroll
    for (int o = 0; o < 8; o++) {
        float* op = out + ((size_t)(n*64+oc0+o)*H + y0)*W + x0;
        op[0] = acc[o][0];
        if (xv) op[1] = acc[o][1];
        if (yv) { op[W] = acc[o][2]; if (xv) op[W+1] = acc[o][3]; }
    }
}

// backward-data conv with FUSED unpool, scalar, OCG oc (21x21 layer)
template<int OCG>
__launch_bounds__(128)
__global__ void conv2f_k(const float* __restrict__ dp, const unsigned char* __restrict__ ib,
                         const float* __restrict__ w, float* __restrict__ out,
                         int H, int W, int Hp, int Wp)
{
    const int n = blockIdx.z, oc0 = blockIdx.y*OCG;
    const int TW = (W+1) >> 1, TH = (H+1) >> 1;
    extern __shared__ float ws[];
    for (int i = threadIdx.x; i < OCG*64*9; i += 128) {
        int oi = i/9, k = i - oi*9;
        ws[oi*12+k] = w[(size_t)oc0*64*9 + i];
    }
    __syncthreads();
    int t = blockIdx.x*128 + threadIdx.x;
    if (t >= TH*TW) return;
    int ty = t / TW, tx = t - ty*TW;
    int poff[3][3];
    #pragma unroll
    for (int a = 0; a < 3; a++) {
        int py = ty - 1 + a; bool rv = (unsigned)py < (unsigned)Hp;
        #pragma unroll
        for (int b = 0; b < 3; b++) {
            int px = tx - 1 + b;
            poff[a][b] = (rv && (unsigned)px < (unsigned)Wp) ? py*Wp+px : -1;
        }
    }
    const int AY[4] = {0,1,1,2};
    const int QY[4] = {1,0,1,0};
    float acc[OCG][4];
    #pragma unroll
    for (int o = 0; o < OCG; o++) { acc[o][0]=0.f; acc[o][1]=0.f; acc[o][2]=0.f; acc[o][3]=0.f; }
    const int PS = Hp*Wp;
    const float* dpp = dp + (size_t)n*64*PS;
    const unsigned char* ibp = ib + (size_t)n*64*PS;
    #pragma unroll 1
    for (int ic = 0; ic < 64; ic++, dpp += PS, ibp += PS) {
        float d[3][3]; int id[3][3];
        #pragma unroll
        for (int a = 0; a < 3; a++)
        #pragma unroll
        for (int b = 0; b < 3; b++) {
            int o2 = poff[a][b];
            bool v2 = (o2 >= 0);
            d[a][b]  = v2 ? dpp[o2] : 0.f;
            id[a][b] = v2 ? (int)ibp[o2] : 4;
        }
        float v[4][4];
        #pragma unroll
        for (int u = 0; u < 4; u++)
        #pragma unroll
        for (int j = 0; j < 4; j++) {
            int a = AY[u], b = AY[j];
            int qq = QY[u]*2 + QY[j];
            v[u][j] = (id[a][b] == qq) ? d[a][b] : 0.f;
        }
        #pragma unroll
        for (int o = 0; o < OCG; o++) {
            float wr[12];
            *(float4*)&wr[0] = *(const float4*)&ws[(o*64+ic)*12];
            *(float4*)&wr[4] = *(const float4*)&ws[(o*64+ic)*12+4];
            wr[8] = ws[(o*64+ic)*12+8];
            #pragma unroll
            for (int u = 0; u < 3; u++)
            #pragma unroll
            for (int vv = 0; vv < 3; vv++) {
                float wv = wr[u*3+vv];
                acc[o][0] += wv*v[u  ][vv  ];
                acc[o][1] += wv*v[u  ][vv+1];
                acc[o][2] += wv*v[u+1][vv  ];
                acc[o][3] += wv*v[u+1][vv+1];
            }
        }
    }
    int y0 = 2*ty, x0 = 2*tx;
    bool xv = (x0+1 < W), yv = (y0+1 < H);
    #pragma unroll
    for (int o = 0; o < OCG; o++) {
        float* op = out + ((size_t)(n*64+oc0+o)*H + y0)*W + x0;
        op[0] = acc[o][0];
        if (xv) op[1] = acc[o][1];
        if (yv) { op[W] = acc[o][2]; if (xv) op[W+1] = acc[o][3]; }
    }
}

__global__ void unpool_fc_k(const float* __restrict__ fcw, const int* __restrict__ cptr,
                            const unsigned char* __restrict__ idx, float* __restrict__ delta)
{
    int t = blockIdx.x*256 + threadIdx.x;
    if (t >= 128*64*100) return;
    int x = t % 10, y = (t / 10) % 10, ch = (t / 100) % 64, n = t / 6400;
    int py = y >> 1, px = x >> 1, j = ((y & 1) << 1) | (x & 1);
    int pi = ((n*64 + ch)*5 + py)*5 + px;
    float val = 0.0f;
    if (idx[pi] == j) {
        int cc = cptr[0];
        val = fcw[cc*1600 + ch*25 + py*5 + px];
    }
    delta[t] = val;
}

__global__ void transw_k(const float* __restrict__ w, float* __restrict__ wt) {
    int t = blockIdx.x*256 + threadIdx.x;
    if (t >= 64*64*9) return;
    int uv = t % 9, ic = (t / 9) % 64, oc = t / 576;
    int u = uv / 3, v = uv % 3;
    wt[(ic*64 + oc)*9 + (2-u)*3 + (2-v)] = w[t];
}

// weight+bias gradient, layers 1..3, packed f32x2 over oc-pairs.
template<int IC, int ICC>
__global__ void wgrad2_k(const float* __restrict__ dp, const unsigned char* __restrict__ ib,
                         const float* __restrict__ in,
                         float* __restrict__ G, int gofs, int bofs,
                         const float* __restrict__ scal, int sidx, int H, int W,
                         int Hp, int Wp)
{
    const int n = blockIdx.y, oc0 = blockIdx.x*4;
    const int DW = W | 1;
    const int PW = (W+2) | 1;
    const int PH = H + 2;
    const int HDW = H*DW, PHW = PH*PW;
    extern __shared__ float sm[];
    ull*   ds2  = (ull*)sm;
    float* ins  = sm + 4*HDW;
    float* bred = ins + ICC*PHW;
    const int tid = threadIdx.x;
    const int lane = tid & 31, icl = tid >> 5;
    const int NT = ICC*32;
    if (tid < 4) bred[tid] = 0.f;
    for (int i = tid; i < 2*HDW; i += NT) {
        int pr = i / HDW, r = i - pr*HDW;
        int y = r / DW, x = r - y*DW;
        float lo = 0.f, hi = 0.f;
        if (x < W) {
            int plane0 = n*64 + oc0 + 2*pr;
            if (ib) {
                if (y < 2*Hp && x < 2*Wp) {
                    int py = y>>1, px = x>>1, j = ((y&1)<<1)|(x&1);
                    size_t pi0 = ((size_t)plane0*Hp + py)*Wp + px;
                    size_t pi1 = pi0 + (size_t)Hp*Wp;
                    if (ib[pi0] == j) lo = dp[pi0];
                    if (ib[pi1] == j) hi = dp[pi1];
                }
            } else {
                size_t b = (size_t)plane0*H*W + y*W + x;
                lo = dp[b]; hi = dp[b + (size_t)H*W];
            }
        }
        ds2[i] = pk(lo, hi);
    }
    __syncthreads();
    #pragma unroll
    for (int pr = 0; pr < 2; pr++) {
        float s0 = 0.f, s1 = 0.f;
        for (int i = tid; i < HDW; i += NT) {
            float lo, hi; upk(ds2[pr*HDW + i], lo, hi);
            s0 += lo; s1 += hi;
        }
        #pragma unroll
        for (int off = 16; off; off >>= 1) {
            s0 += __shfl_xor_sync(0xffffffffu, s0, off);
            s1 += __shfl_xor_sync(0xffffffffu, s1, off);
        }
        if (lane == 0) { atomicAdd(&bred[2*pr], s0); atomicAdd(&bred[2*pr+1], s1); }
    }
    const float s  = scal[sidx];
    const float sb = scal[sidx+1];
    for (int chunk = 0; chunk < IC; chunk += ICC) {
        __syncthreads();
        for (int i = tid; i < ICC*PHW; i += NT) {
            int icp = i / PHW, r = i - icp*PHW;
            int yy = r / PW - 1, xx = r - (yy+1)*PW - 1;
            float val = 0.f;
            if ((unsigned)yy < (unsigned)H && (unsigned)xx < (unsigned)W)
                val = in[(size_t)(n*IC + chunk + icp)*H*W + yy*W + xx];
            ins[i] = val;
        }
        __syncthreads();
        ull acc[2][9];
        #pragma unroll
        for (int pr = 0; pr < 2; pr++)
        #pragma unroll
        for (int k = 0; k < 9; k++) acc[pr][k] = 0ull;
        const float* myin = ins + icl*PHW;
        for (int y = lane; y < H; y += 32) {
            const float* r0p = myin + y*PW;
            const float* r1p = r0p + PW;
            const float* r2p = r1p + PW;
            const ull* d0y = ds2 + y*DW;
            const ull* d1y = ds2 + HDW + y*DW;
            float f;
            f = r0p[0]; ull pa0 = pk(f,f);
            f = r0p[1]; ull pa1 = pk(f,f);
            f = r1p[0]; ull pb0 = pk(f,f);
            f = r1p[1]; ull pb1 = pk(f,f);
            f = r2p[0]; ull pc0 = pk(f,f);
            f = r2p[1]; ull pc1 = pk(f,f);
            #pragma unroll 2
            for (int x = 0; x < W; x++) {
                float na = r0p[x+2], nb = r1p[x+2], nc = r2p[x+2];
                ull pa2 = pk(na,na), pb2 = pk(nb,nb), pc2 = pk(nc,nc);
                ull d0 = d0y[x], d1 = d1y[x];
                ffma2(acc[0][0], d0, pa0); ffma2(acc[0][1], d0, pa1); ffma2(acc[0][2], d0, pa2);
                ffma2(acc[0][3], d0, pb0); ffma2(acc[0][4], d0, pb1); ffma2(acc[0][5], d0, pb2);
                ffma2(acc[0][6], d0, pc0); ffma2(acc[0][7], d0, pc1); ffma2(acc[0][8], d0, pc2);
                ffma2(acc[1][0], d1, pa0); ffma2(acc[1][1], d1, pa1); ffma2(acc[1][2], d1, pa2);
                ffma2(acc[1][3], d1, pb0); ffma2(acc[1][4], d1, pb1); ffma2(acc[1][5], d1, pb2);
                ffma2(acc[1][6], d1, pc0); ffma2(acc[1][7], d1, pc1); ffma2(acc[1][8], d1, pc2);
                pa0 = pa1; pa1 = pa2; pb0 = pb1; pb1 = pb2; pc0 = pc1; pc1 = pc2;
            }
        }
        #pragma unroll
        for (int pr = 0; pr < 2; pr++)
        #pragma unroll
        for (int k = 0; k < 9; k++) {
            float v0, v1; upk(acc[pr][k], v0, v1);
            #pragma unroll
            for (int off = 16; off; off >>= 1) {
                v0 += __shfl_xor_sync(0xffffffffu, v0, off);
                v1 += __shfl_xor_sync(0xffffffffu, v1, off);
            }
            if (lane == 0) {
                size_t base = (size_t)n*F2 + gofs;
                G[base + ((size_t)(oc0+2*pr  )*IC + chunk + icl)*9 + k] = s*v0;
                G[base + ((size_t)(oc0+2*pr+1)*IC + chunk + icl)*9 + k] = s*v1;
            }
        }
    }
    __syncthreads();
    if (tid < 4) G[(size_t)n*F2 + bofs + oc0 + tid] = sb*bred[tid];
}

// layer-0 weight+bias gradient with fused unpool (no d0 buffer)
__global__ void wgrad0_k(const float* __restrict__ dp0, const unsigned char* __restrict__ i0,
                         const float* __restrict__ xp, float* __restrict__ G,
                         const float* __restrict__ scal)
{
    const int n = blockIdx.y, oh = blockIdx.x;
    extern __shared__ float sm[];
    float* ins  = sm;                 // 3*86*87
    float* ds   = ins + 22446;        // 84*85
    float* red  = ds + 7140;          // 3*9*84
    float* bred = red + 2268;         // 8
    const int tid = threadIdx.x;      // 256
    for (int i = tid; i < 3*86*87; i += 256) {
        int icp = i/(86*87), r = i - icp*(86*87);
        int yy = r/87 - 1, xx = r - (yy+1)*87 - 1;
        float val = 0.f;
        if ((unsigned)yy < 84u && (unsigned)xx < 84u)
            val = xp[(size_t)(n*3+icp)*7056 + yy*84 + xx];
        ins[i] = val;
    }
    const float s = scal[0], sb = scal[1];
    const int icl = tid / 84, rg = tid - icl*84;
    for (int oc8 = 0; oc8 < 32; oc8++) {
        const int oc = oh*32 + oc8;
        __syncthreads();
        const float* dpp = dp0 + (size_t)(n*64+oc)*1764;
        const unsigned char* ipp = i0 + (size_t)(n*64+oc)*1764;
        for (int i = tid; i < 84*85; i += 256) {
            int y = i/85, x = i - y*85;
            float val = 0.f;
            if (x < 84) {
                int py = y>>1, px = x>>1, j = ((y&1)<<1)|(x&1);
                int pi = py*42 + px;
                if (ipp[pi] == j) val = dpp[pi];
            }
            ds[i] = val;
        }
        __syncthreads();
        float bp = 0.f;
        for (int i = tid; i < 84*85; i += 256) bp += ds[i];
        #pragma unroll
        for (int off = 16; off; off >>= 1) bp += __shfl_xor_sync(0xffffffffu, bp, off);
        if ((tid & 31) == 0) bred[tid >> 5] = bp;
        float acc[9];
        #pragma unroll
        for (int k = 0; k < 9; k++) acc[k] = 0.f;
        if (tid < 252) {
            const float* r0p = ins + icl*7482 + rg*87;
            const float* r1p = r0p + 87;
            const float* r2p = r1p + 87;
            const float* dsy = ds + rg*85;
            float a0=r0p[0],a1=r0p[1],b0=r1p[0],b1=r1p[1],c0=r2p[0],c1=r2p[1];
            #pragma unroll 2
            for (int x = 0; x < 84; x++) {
                float a2=r0p[x+2], b2=r1p[x+2], c2=r2p[x+2];
                float d = dsy[x];
                acc[0]+=d*a0; acc[1]+=d*a1; acc[2]+=d*a2;
                acc[3]+=d*b0; acc[4]+=d*b1; acc[5]+=d*b2;
                acc[6]+=d*c0; acc[7]+=d*c1; acc[8]+=d*c2;
                a0=a1;a1=a2;b0=b1;b1=b2;c0=c1;c1=c2;
            }
            #pragma unroll
            for (int k = 0; k < 9; k++) red[(icl*9+k)*84 + rg] = acc[k];
        }
        __syncthreads();
        if (tid == 0) {
            float a = 0.f;
            #pragma unroll
            for (int wq = 0; wq < 8; wq++) a += bred[wq];
            G[(size_t)n*F2 + OB0 + oc] = sb*a;
        }
        for (int o = tid; o < 27; o += 256) {
            float t2 = 0.f;
            for (int r = 0; r < 84; r++) t2 += red[o*84 + r];
            int icg = o/9, uv = o - icg*9;
            G[(size_t)n*F2 + OW0 + (oc*3 + icg)*9 + uv] = s*t2;
        }
    }
}

__global__ void copyp3_k(const float* __restrict__ p3, float* __restrict__ G,
                         const float* __restrict__ scal)
{
    int t = blockIdx.x*256 + threadIdx.x;
    if (t >= 128*1600) return;
    int n = t / 1600, j = t - n*1600;
    G[(size_t)n*F2 + OFC + j] = scal[8]*p3[t];
}

// K partials: 128 split-F blocks, 4x4 register tiles over the 64x64 tile
__launch_bounds__(256)
__global__ void gemm2_k(const float* __restrict__ G, float* __restrict__ part)
{
    const int sp = blockIdx.x;
    const int f0 = sp*896;
    __shared__ float As[16][68], Bs[16][68];
    const int tid = threadIdx.x;
    const int row = tid >> 2, kq = tid & 3;
    const int ty = tid >> 4, tx = tid & 15;
    float acc[4][4];
    #pragma unroll
    for (int i = 0; i < 4; i++)
    #pragma unroll
    for (int j = 0; j < 4; j++) acc[i][j] = 0.f;
    const float* Ap = G + (size_t)row*F2 + f0 + kq*4;
    const float* Bp = G + (size_t)(64+row)*F2 + f0 + kq*4;
    #pragma unroll 1
    for (int fs = 0; fs < 56; fs++) {
        float4 a4 = *(const float4*)(Ap + fs*16);
        float4 b4 = *(const float4*)(Bp + fs*16);
        __syncthreads();
        As[kq*4+0][row] = a4.x; As[kq*4+1][row] = a4.y;
        As[kq*4+2][row] = a4.z; As[kq*4+3][row] = a4.w;
        Bs[kq*4+0][row] = b4.x; Bs[kq*4+1][row] = b4.y;
        Bs[kq*4+2][row] = b4.z; Bs[kq*4+3][row] = b4.w;
        __syncthreads();
        #pragma unroll
        for (int k = 0; k < 16; k++) {
            float4 av = *(const float4*)&As[k][ty*4];
            float4 bv = *(const float4*)&Bs[k][tx*4];
            float a[4] = {av.x, av.y, av.z, av.w};
            float b[4] = {bv.x, bv.y, bv.z, bv.w};
            #pragma unroll
            for (int i = 0; i < 4; i++)
            #pragma unroll
            for (int j = 0; j < 4; j++)
                acc[i][j] += a[i]*b[j];
        }
    }
    float* pp = part + (size_t)sp*4096;
    #pragma unroll
    for (int i = 0; i < 4; i++)
    #pragma unroll
    for (int j = 0; j < 4; j++)
        pp[(ty*4+i)*64 + (tx*4+j)] = acc[i][j];
}

__global__ void reduce_k(const float* __restrict__ part, const float* __restrict__ scal,
                         float* __restrict__ out)
{
    int t = blockIdx.x*256 + threadIdx.x;
    if (t >= 4096) return;
    float a = scal[9]*scal[9];
    #pragma unroll 8
    for (int sp = 0; sp < 128; sp++) a += part[sp*4096 + t];
    out[t] = a;
}

// ---------------- host ----------------
extern "C" void kernel_launch(void* const* d_in, const int* in_sizes, int n_in,
                              void* d_out, int out_size)
{
    const float* x1  = (const float*)d_in[0];
    const float* x2  = (const float*)d_in[1];
    const float* scal= (const float*)d_in[2];
    const int*   cp  = (const int*)  d_in[3];
    const float* w0  = (const float*)d_in[4];
    const float* b0  = (const float*)d_in[5];
    const float* w1  = (const float*)d_in[6];
    const float* b1  = (const float*)d_in[7];
    const float* w2  = (const float*)d_in[8];
    const float* b2  = (const float*)d_in[9];
    const float* w3  = (const float*)d_in[10];
    const float* b3  = (const float*)d_in[11];
    const float* fcw = (const float*)d_in[12];
    float* out = (float*)d_out;

    float *xp,*p0,*dp0,*p1,*dp1,*p2,*d3,*dp2,*p3,*wt,*G,*part;
    unsigned char *i0,*i1,*i2,*i3;
    cudaGetSymbolAddress((void**)&xp,  g_x);
    cudaGetSymbolAddress((void**)&p0,  g_p0);
    cudaGetSymbolAddress((void**)&dp0, g_dp0);
    cudaGetSymbolAddress((void**)&i0,  g_i0);
    cudaGetSymbolAddress((void**)&p1,  g_p1);
    cudaGetSymbolAddress((void**)&dp1, g_dp1);
    cudaGetSymbolAddress((void**)&i1,  g_i1);
    cudaGetSymbolAddress((void**)&p2,  g_p2);
    cudaGetSymbolAddress((void**)&d3,  g_d3);
    cudaGetSymbolAddress((void**)&dp2, g_dp2);
    cudaGetSymbolAddress((void**)&i2,  g_i2);
    cudaGetSymbolAddress((void**)&p3,  g_p3);
    cudaGetSymbolAddress((void**)&i3,  g_i3);
    cudaGetSymbolAddress((void**)&wt,  g_wt);
    cudaGetSymbolAddress((void**)&G,   g_G);
    cudaGetSymbolAddress((void**)&part,g_part);

    const int smW0 = (22446 + 7140 + 2268 + 8)*4;
    const int sm42 = (4*42*43)*4 + (8*44*45)*4 + 16;
    const int sm21 = (4*21*21)*4 + (8*23*23)*4 + 16;
    const int sm10 = (4*10*11)*4 + (8*12*13)*4 + 16;

    static bool init = false;
    if (!init) {
        init = true;
        cudaFuncSetAttribute(wgrad0_k, cudaFuncAttributeMaxDynamicSharedMemorySize, smW0);
        cudaFuncSetAttribute(wgrad2_k<64,8>, cudaFuncAttributeMaxDynamicSharedMemorySize, sm42);
        cudaFuncSetAttribute(conv2f_k<8>, cudaFuncAttributeMaxDynamicSharedMemorySize, 8*64*12*4);
    }

    // ---- forward (conv+relu+pool fused) ----
    pack_x_k<<<(128*3*84*84 + 255)/256, 256>>>(x1, x2, xp);
    zpad_k<<<(128*(F2-F) + 255)/256, 256>>>(G);
    convpool_k<3,1,1,true> <<<dim3(14,8,128),128>>>(xp, w0, b0, p0, i0, 84, 84, 42, 42);
    convpool8p_k<<<dim3(4,8,128),128>>>(p0, w1, b1, p1, i1, 42, 42, 21, 21);
    convpool_k<64,1,1,false><<<dim3(1,8,128),128>>>(p1, w2, b2, p2, i2, 21, 21, 10, 10);
    convpool_k<64,5,25,true><<<dim3(1,8,26),128>>>(p2, w3, b3, p3, i3, 10, 10, 5, 5);

    // ---- backward (scalar output c); unpool fused into conv loads ----
    unpool_fc_k<<<(128*64*100 + 255)/256, 256>>>(fcw, cp, i3, d3);
    transw_k<<<144,256>>>(w3, wt + 0*WTS);
    transw_k<<<144,256>>>(w2, wt + 1*WTS);
    transw_k<<<144,256>>>(w1, wt + 2*WTS);
    conv2_k<64,5,25><<<dim3(1,8,26),128>>>(d3, wt + 0*WTS, dp2, 10, 10);
    conv2f_k<8><<<dim3(1,8,128),128, 8*64*12*4>>>(dp2, i2, wt + 1*WTS, dp1, 21, 21, 10, 10);
    conv2f8p_k<<<dim3(4,8,128),128>>>(dp1, i1, wt + 2*WTS, dp0, 42, 42, 21, 21);

    // ---- per-example gradients -> scaled feature matrix G ----
    wgrad0_k<<<dim3(2,128), 256, smW0>>>(dp0, i0, xp, G, scal);
    wgrad2_k<64,8><<<dim3(16,128), 256, sm42>>>(dp1, i1, p0, G, OW1, OB1, scal, 2, 42, 42, 21, 21);
    wgrad2_k<64,8><<<dim3(16,128), 256, sm21>>>(dp2, i2, p1, G, OW2, OB2, scal, 4, 21, 21, 10, 10);
    wgrad2_k<64,8><<<dim3(16,128), 256, sm10>>>(d3, nullptr, p2, G, OW3, OB3, scal, 6, 10, 10, 5, 5);
    copyp3_k<<<(128*1600 + 255)/256, 256>>>(p3, G, scal);

    // ---- K = G1 G2^T + s_fcb^2 ----
    gemm2_k<<<128, 256>>>(G, part);
    reduce_k<<<16, 256>>>(part, scal, out);
}

// round 13
// speedup vs baseline: 1.0514x; 1.0514x over previous
#include <cuda_runtime.h>

typedef unsigned long long ull;

__device__ __forceinline__ ull pk(float lo, float hi) {
    ull r; asm("mov.b64 %0,{%1,%2};" : "=l"(r) : "f"(lo), "f"(hi)); return r;
}
__device__ __forceinline__ void upk(ull v, float& lo, float& hi) {
    asm("mov.b64 {%0,%1},%2;" : "=f"(lo), "=f"(hi) : "l"(v));
}
__device__ __forceinline__ void ffma2(ull& d, ull a, ull b) {
    asm("fma.rn.f32x2 %0,%1,%2,%0;" : "+l"(d) : "l"(a), "l"(b));
}

// ---------------- constants ----------------
constexpr int F  = 114176;
constexpr int F2 = 114688;
constexpr int OW0 = 0, OB0 = 1728, OW1 = 1792, OB1 = 38656, OW2 = 38720,
              OB2 = 75584, OW3 = 75648, OB3 = 112512, OFC = 112576;
constexpr int WTS = 64*64*9;

// ---------------- scratch ----------------
__device__ float g_x  [128*3*84*84];
__device__ float g_p0 [128*64*42*42];
__device__ float g_dp0[128*64*42*42];
__device__ unsigned char g_i0[128*64*42*42];
__device__ float g_p1 [128*64*21*21];
__device__ float g_dp1[128*64*21*21];
__device__ unsigned char g_i1[128*64*21*21];
__device__ float g_p2 [128*64*10*10];
__device__ float g_d3 [128*64*10*10];
__device__ float g_dp2[128*64*10*10];
__device__ unsigned char g_i2[128*64*10*10];
__device__ float g_p3 [128*64*5*5];
__device__ unsigned char g_i3[128*64*5*5];
__device__ float g_wt [3*WTS];
__device__ float g_G  [128*(size_t)F2];
__device__ float g_part[128*4096];

// ---------------- kernels ----------------
__global__ void pack_x_k(const float* __restrict__ x1, const float* __restrict__ x2,
                         float* __restrict__ xo) {
    int t = blockIdx.x*256 + threadIdx.x;
    const int P = 3*84*84;
    if (t >= 128*P) return;
    int n = t / P, k = t - n*P;
    xo[t] = (n < 64) ? x1[n*P + k] : x2[(n-64)*P + k];
}

__global__ void zpad_k(float* __restrict__ G) {
    int t = blockIdx.x*256 + threadIdx.x;
    if (t >= 128*(F2-F)) return;
    int n = t >> 9, j = t & 511;
    G[(size_t)n*F2 + F + j] = 0.f;
}

// fused conv3x3(SAME)+bias+relu+2x2 maxpool; 8 oc x 4 px register tiles
template<int IC, int NPB, int PXT, bool VEC>
__launch_bounds__(128)
__global__ void convpool_k(const float* __restrict__ in, const float* __restrict__ w,
                           const float* __restrict__ bias, float* __restrict__ p,
                           unsigned char* __restrict__ idx,
                           int H, int W, int Hp, int Wp)
{
    const int oc0 = blockIdx.y*8;
    __shared__ float ws[8*IC*12];
    __shared__ float bs[8];
    for (int i = threadIdx.x; i < 8*IC*9; i += 128) {
        int oi = i/9, k = i - oi*9;
        ws[oi*12+k] = w[(size_t)oc0*IC*9 + i];
    }
    if (threadIdx.x < 8) bs[threadIdx.x] = bias[oc0+threadIdx.x];
    __syncthreads();
    int n, t;
    if (NPB == 1) {
        n = blockIdx.z; t = blockIdx.x*128 + threadIdx.x;
        if (t >= Hp*Wp) return;
    } else {
        int q = threadIdx.x / PXT; t = threadIdx.x - q*PXT;
        n = blockIdx.z*NPB + q;
        if (q >= NPB || n >= 128) return;
    }
    int py = t / Wp, px = t - py*Wp;
    int y0 = py*2, x0 = px*2;
    bool rv[4];
    #pragma unroll
    for (int u = 0; u < 4; u++) { int yy = y0-1+u; rv[u] = (unsigned)yy < (unsigned)H; }
    const bool ax = (x0 >= 2);
    const bool cx = (x0 + 2 < W);
    int offs[4][4];
    if (!VEC) {
        #pragma unroll
        for (int u = 0; u < 4; u++)
        #pragma unroll
        for (int j = 0; j < 4; j++) {
            int xx = x0-1+j;
            offs[u][j] = (rv[u] && (unsigned)xx < (unsigned)W) ? (y0-1+u)*W+xx : -1;
        }
    }
    float acc[8][4];
    #pragma unroll
    for (int o = 0; o < 8; o++) {
        float b = bs[o];
        acc[o][0]=b; acc[o][1]=b; acc[o][2]=b; acc[o][3]=b;
    }
    const int HW = H*W;
    const float* ip = in + (size_t)n*IC*HW;
    const float* bp = ip + (y0-1)*W + x0;
    #pragma unroll 1
    for (int ic = 0; ic < IC; ic++, ip += HW, bp += HW) {
        float v[4][4];
        if (VEC) {
            #pragma unroll
            for (int u = 0; u < 4; u++) {
                const float* rp = bp + u*W;
                float2 A = (rv[u] && ax) ? *(const float2*)(rp - 2) : make_float2(0.f, 0.f);
                float2 B =  rv[u]        ? *(const float2*)(rp    ) : make_float2(0.f, 0.f);
                float2 C = (rv[u] && cx) ? *(const float2*)(rp + 2) : make_float2(0.f, 0.f);
                v[u][0] = A.y; v[u][1] = B.x; v[u][2] = B.y; v[u][3] = C.x;
            }
        } else {
            #pragma unroll
            for (int u = 0; u < 4; u++)
            #pragma unroll
            for (int j = 0; j < 4; j++)
                v[u][j] = (offs[u][j] >= 0) ? ip[offs[u][j]] : 0.0f;
        }
        #pragma unroll
        for (int o = 0; o < 8; o++) {
            float wr[12];
            *(float4*)&wr[0] = *(const float4*)&ws[(o*IC+ic)*12];
            *(float4*)&wr[4] = *(const float4*)&ws[(o*IC+ic)*12+4];
            wr[8] = ws[(o*IC+ic)*12+8];
            #pragma unroll
            for (int u = 0; u < 3; u++)
            #pragma unroll
            for (int vv = 0; vv < 3; vv++) {
                float wv = wr[u*3+vv];
                acc[o][0] += wv*v[u  ][vv  ];
                acc[o][1] += wv*v[u  ][vv+1];
                acc[o][2] += wv*v[u+1][vv  ];
                acc[o][3] += wv*v[u+1][vv+1];
            }
        }
    }
    #pragma unroll
    for (int o = 0; o < 8; o++) {
        float a0 = fmaxf(acc[o][0],0.f), a1 = fmaxf(acc[o][1],0.f),
              a2 = fmaxf(acc[o][2],0.f), a3 = fmaxf(acc[o][3],0.f);
        float m = a0; int am = 0;
        if (a1 > m) { m = a1; am = 1; }
        if (a2 > m) { m = a2; am = 2; }
        if (a3 > m) { m = a3; am = 3; }
        size_t ob = ((size_t)(n*64+oc0+o)*Hp + py)*Wp + px;
        p[ob] = m;
        idx[ob] = (m > 0.f) ? (unsigned char)am : (unsigned char)4;
    }
}

// 16 oc x 4 px fused conv+bias+relu+pool, IC=64, VEC (42x42 layer)
__launch_bounds__(128)
__global__ void convpool16_k(const float* __restrict__ in, const float* __restrict__ w,
                             const float* __restrict__ bias, float* __restrict__ p,
                             unsigned char* __restrict__ idx,
                             int H, int W, int Hp, int Wp)
{
    const int oc0 = blockIdx.y*16;
    extern __shared__ float ws[];   // 16*64*12
    __shared__ float bs[16];
    for (int i = threadIdx.x; i < 16*64*9; i += 128) {
        int oi = i/9, k = i - oi*9;
        ws[oi*12+k] = w[(size_t)oc0*64*9 + i];
    }
    if (threadIdx.x < 16) bs[threadIdx.x] = bias[oc0+threadIdx.x];
    __syncthreads();
    const int n = blockIdx.z;
    int t = blockIdx.x*128 + threadIdx.x;
    if (t >= Hp*Wp) return;
    int py = t / Wp, px = t - py*Wp;
    int y0 = py*2, x0 = px*2;
    bool rv[4];
    #pragma unroll
    for (int u = 0; u < 4; u++) { int yy = y0-1+u; rv[u] = (unsigned)yy < (unsigned)H; }
    const bool ax = (x0 >= 2);
    const bool cx = (x0 + 2 < W);
    float acc[16][4];
    #pragma unroll
    for (int o = 0; o < 16; o++) {
        float b = bs[o];
        acc[o][0]=b; acc[o][1]=b; acc[o][2]=b; acc[o][3]=b;
    }
    const int HW = H*W;
    const float* bp = in + (size_t)n*64*HW + (y0-1)*W + x0;
    #pragma unroll 1
    for (int ic = 0; ic < 64; ic++, bp += HW) {
        float v[4][4];
        #pragma unroll
        for (int u = 0; u < 4; u++) {
            const float* rp = bp + u*W;
            float2 A = (rv[u] && ax) ? *(const float2*)(rp - 2) : make_float2(0.f, 0.f);
            float2 B =  rv[u]        ? *(const float2*)(rp    ) : make_float2(0.f, 0.f);
            float2 C = (rv[u] && cx) ? *(const float2*)(rp + 2) : make_float2(0.f, 0.f);
            v[u][0] = A.y; v[u][1] = B.x; v[u][2] = B.y; v[u][3] = C.x;
        }
        #pragma unroll
        for (int o = 0; o < 16; o++) {
            float wr[12];
            *(float4*)&wr[0] = *(const float4*)&ws[(o*64+ic)*12];
            *(float4*)&wr[4] = *(const float4*)&ws[(o*64+ic)*12+4];
            wr[8] = ws[(o*64+ic)*12+8];
            #pragma unroll
            for (int u = 0; u < 3; u++)
            #pragma unroll
            for (int vv = 0; vv < 3; vv++) {
                float wv = wr[u*3+vv];
                acc[o][0] += wv*v[u  ][vv  ];
                acc[o][1] += wv*v[u  ][vv+1];
                acc[o][2] += wv*v[u+1][vv  ];
                acc[o][3] += wv*v[u+1][vv+1];
            }
        }
    }
    #pragma unroll
    for (int o = 0; o < 16; o++) {
        float a0 = fmaxf(acc[o][0],0.f), a1 = fmaxf(acc[o][1],0.f),
              a2 = fmaxf(acc[o][2],0.f), a3 = fmaxf(acc[o][3],0.f);
        float m = a0; int am = 0;
        if (a1 > m) { m = a1; am = 1; }
        if (a2 > m) { m = a2; am = 2; }
        if (a3 > m) { m = a3; am = 3; }
        size_t ob = ((size_t)(n*64+oc0+o)*Hp + py)*Wp + px;
        p[ob] = m;
        idx[ob] = (m > 0.f) ? (unsigned char)am : (unsigned char)4;
    }
}

// plain backward-data conv (10x10 layer only), 8 oc
template<int IC, int NPB, int PXT>
__launch_bounds__(128)
__global__ void conv2_k(const float* __restrict__ in, const float* __restrict__ w,
                        float* __restrict__ out, int H, int W)
{
    const int n0 = blockIdx.z, oc0 = blockIdx.y*8;
    const int TW = (W+1) >> 1;
    __shared__ float ws[8*IC*12];
    for (int i = threadIdx.x; i < 8*IC*9; i += 128) {
        int oi = i/9, k = i - oi*9;
        ws[oi*12+k] = w[(size_t)oc0*IC*9 + i];
    }
    __syncthreads();
    int q = threadIdx.x / PXT, t = threadIdx.x - q*PXT;
    int n = n0*NPB + q;
    if (q >= NPB || n >= 128) return;
    int ty = t / TW, tx = t - ty*TW;
    int y0 = ty*2, x0 = tx*2;
    int offs[4][4];
    #pragma unroll
    for (int u = 0; u < 4; u++) {
        int yy = y0-1+u; bool rv = (unsigned)yy < (unsigned)H;
        #pragma unroll
        for (int j = 0; j < 4; j++) {
            int xx = x0-1+j;
            offs[u][j] = (rv && (unsigned)xx < (unsigned)W) ? yy*W+xx : -1;
        }
    }
    float acc[8][4];
    #pragma unroll
    for (int o = 0; o < 8; o++) { acc[o][0]=0.f; acc[o][1]=0.f; acc[o][2]=0.f; acc[o][3]=0.f; }
    const float* ip = in + (size_t)n*IC*H*W;
    #pragma unroll 1
    for (int ic = 0; ic < IC; ic++, ip += H*W) {
        float v[4][4];
        #pragma unroll
        for (int u = 0; u < 4; u++)
        #pragma unroll
        for (int j = 0; j < 4; j++)
            v[u][j] = (offs[u][j] >= 0) ? ip[offs[u][j]] : 0.0f;
        #pragma unroll
        for (int o = 0; o < 8; o++) {
            float wr[12];
            *(float4*)&wr[0] = *(const float4*)&ws[(o*IC+ic)*12];
            *(float4*)&wr[4] = *(const float4*)&ws[(o*IC+ic)*12+4];
            wr[8] = ws[(o*IC+ic)*12+8];
            #pragma unroll
            for (int u = 0; u < 3; u++)
            #pragma unroll
            for (int vv = 0; vv < 3; vv++) {
                float wv = wr[u*3+vv];
                acc[o][0] += wv*v[u  ][vv  ];
                acc[o][1] += wv*v[u  ][vv+1];
                acc[o][2] += wv*v[u+1][vv  ];
                acc[o][3] += wv*v[u+1][vv+1];
            }
        }
    }
    bool xv = (x0+1 < W), yv = (y0+1 < H);
    #pragma unroll
    for (int o = 0; o < 8; o++) {
        float* op = out + ((size_t)(n*64+oc0+o)*H + y0)*W + x0;
        op[0] = acc[o][0];
        if (xv) op[1] = acc[o][1];
        if (yv) { op[W] = acc[o][2]; if (xv) op[W+1] = acc[o][3]; }
    }
}

// backward-data conv with FUSED unpool, OCG oc x 4 px
template<int OCG>
__launch_bounds__(128)
__global__ void conv2f_k(const float* __restrict__ dp, const unsigned char* __restrict__ ib,
                         const float* __restrict__ w, float* __restrict__ out,
                         int H, int W, int Hp, int Wp)
{
    const int n = blockIdx.z, oc0 = blockIdx.y*OCG;
    const int TW = (W+1) >> 1, TH = (H+1) >> 1;
    extern __shared__ float ws[];   // OCG*64*12
    for (int i = threadIdx.x; i < OCG*64*9; i += 128) {
        int oi = i/9, k = i - oi*9;
        ws[oi*12+k] = w[(size_t)oc0*64*9 + i];
    }
    __syncthreads();
    int t = blockIdx.x*128 + threadIdx.x;
    if (t >= TH*TW) return;
    int ty = t / TW, tx = t - ty*TW;
    int poff[3][3];
    #pragma unroll
    for (int a = 0; a < 3; a++) {
        int py = ty - 1 + a; bool rv = (unsigned)py < (unsigned)Hp;
        #pragma unroll
        for (int b = 0; b < 3; b++) {
            int px = tx - 1 + b;
            poff[a][b] = (rv && (unsigned)px < (unsigned)Wp) ? py*Wp+px : -1;
        }
    }
    const int AY[4] = {0,1,1,2};
    const int QY[4] = {1,0,1,0};
    float acc[OCG][4];
    #pragma unroll
    for (int o = 0; o < OCG; o++) { acc[o][0]=0.f; acc[o][1]=0.f; acc[o][2]=0.f; acc[o][3]=0.f; }
    const int PS = Hp*Wp;
    const float* dpp = dp + (size_t)n*64*PS;
    const unsigned char* ibp = ib + (size_t)n*64*PS;
    #pragma unroll 1
    for (int ic = 0; ic < 64; ic++, dpp += PS, ibp += PS) {
        float d[3][3]; int id[3][3];
        #pragma unroll
        for (int a = 0; a < 3; a++)
        #pragma unroll
        for (int b = 0; b < 3; b++) {
            int o2 = poff[a][b];
            bool v2 = (o2 >= 0);
            d[a][b]  = v2 ? dpp[o2] : 0.f;
            id[a][b] = v2 ? (int)ibp[o2] : 4;
        }
        float v[4][4];
        #pragma unroll
        for (int u = 0; u < 4; u++)
        #pragma unroll
        for (int j = 0; j < 4; j++) {
            int a = AY[u], b = AY[j];
            int qq = QY[u]*2 + QY[j];
            v[u][j] = (id[a][b] == qq) ? d[a][b] : 0.f;
        }
        #pragma unroll
        for (int o = 0; o < OCG; o++) {
            float wr[12];
            *(float4*)&wr[0] = *(const float4*)&ws[(o*64+ic)*12];
            *(float4*)&wr[4] = *(const float4*)&ws[(o*64+ic)*12+4];
            wr[8] = ws[(o*64+ic)*12+8];
            #pragma unroll
            for (int u = 0; u < 3; u++)
            #pragma unroll
            for (int vv = 0; vv < 3; vv++) {
                float wv = wr[u*3+vv];
                acc[o][0] += wv*v[u  ][vv  ];
                acc[o][1] += wv*v[u  ][vv+1];
                acc[o][2] += wv*v[u+1][vv  ];
                acc[o][3] += wv*v[u+1][vv+1];
            }
        }
    }
    int y0 = 2*ty, x0 = 2*tx;
    bool xv = (x0+1 < W), yv = (y0+1 < H);
    #pragma unroll
    for (int o = 0; o < OCG; o++) {
        float* op = out + ((size_t)(n*64+oc0+o)*H + y0)*W + x0;
        op[0] = acc[o][0];
        if (xv) op[1] = acc[o][1];
        if (yv) { op[W] = acc[o][2]; if (xv) op[W+1] = acc[o][3]; }
    }
}

__global__ void unpool_fc_k(const float* __restrict__ fcw, const int* __restrict__ cptr,
                            const unsigned char* __restrict__ idx, float* __restrict__ delta)
{
    int t = blockIdx.x*256 + threadIdx.x;
    if (t >= 128*64*100) return;
    int x = t % 10, y = (t / 10) % 10, ch = (t / 100) % 64, n = t / 6400;
    int py = y >> 1, px = x >> 1, j = ((y & 1) << 1) | (x & 1);
    int pi = ((n*64 + ch)*5 + py)*5 + px;
    float val = 0.0f;
    if (idx[pi] == j) {
        int cc = cptr[0];
        val = fcw[cc*1600 + ch*25 + py*5 + px];
    }
    delta[t] = val;
}

__global__ void transw_k(const float* __restrict__ w, float* __restrict__ wt) {
    int t = blockIdx.x*256 + threadIdx.x;
    if (t >= 64*64*9) return;
    int uv = t % 9, ic = (t / 9) % 64, oc = t / 576;
    int u = uv / 3, v = uv % 3;
    wt[(ic*64 + oc)*9 + (2-u)*3 + (2-v)] = w[t];
}

// weight+bias gradient, layers 1..3, packed f32x2 over oc-pairs.
template<int IC, int ICC>
__global__ void wgrad2_k(const float* __restrict__ dp, const unsigned char* __restrict__ ib,
                         const float* __restrict__ in,
                         float* __restrict__ G, int gofs, int bofs,
                         const float* __restrict__ scal, int sidx, int H, int W,
                         int Hp, int Wp)
{
    const int n = blockIdx.y, oc0 = blockIdx.x*4;
    const int DW = W | 1;
    const int PW = (W+2) | 1;
    const int PH = H + 2;
    const int HDW = H*DW, PHW = PH*PW;
    extern __shared__ float sm[];
    ull*   ds2  = (ull*)sm;
    float* ins  = sm + 4*HDW;
    float* bred = ins + ICC*PHW;
    const int tid = threadIdx.x;
    const int lane = tid & 31, icl = tid >> 5;
    const int NT = ICC*32;
    if (tid < 4) bred[tid] = 0.f;
    for (int i = tid; i < 2*HDW; i += NT) {
        int pr = i / HDW, r = i - pr*HDW;
        int y = r / DW, x = r - y*DW;
        float lo = 0.f, hi = 0.f;
        if (x < W) {
            int plane0 = n*64 + oc0 + 2*pr;
            if (ib) {
                if (y < 2*Hp && x < 2*Wp) {
                    int py = y>>1, px = x>>1, j = ((y&1)<<1)|(x&1);
                    size_t pi0 = ((size_t)plane0*Hp + py)*Wp + px;
                    size_t pi1 = pi0 + (size_t)Hp*Wp;
                    if (ib[pi0] == j) lo = dp[pi0];
                    if (ib[pi1] == j) hi = dp[pi1];
                }
            } else {
                size_t b = (size_t)plane0*H*W + y*W + x;
                lo = dp[b]; hi = dp[b + (size_t)H*W];
            }
        }
        ds2[i] = pk(lo, hi);
    }
    __syncthreads();
    #pragma unroll
    for (int pr = 0; pr < 2; pr++) {
        float s0 = 0.f, s1 = 0.f;
        for (int i = tid; i < HDW; i += NT) {
            float lo, hi; upk(ds2[pr*HDW + i], lo, hi);
            s0 += lo; s1 += hi;
        }
        #pragma unroll
        for (int off = 16; off; off >>= 1) {
            s0 += __shfl_xor_sync(0xffffffffu, s0, off);
            s1 += __shfl_xor_sync(0xffffffffu, s1, off);
        }
        if (lane == 0) { atomicAdd(&bred[2*pr], s0); atomicAdd(&bred[2*pr+1], s1); }
    }
    const float s  = scal[sidx];
    const float sb = scal[sidx+1];
    for (int chunk = 0; chunk < IC; chunk += ICC) {
        __syncthreads();
        for (int i = tid; i < ICC*PHW; i += NT) {
            int icp = i / PHW, r = i - icp*PHW;
            int yy = r / PW - 1, xx = r - (yy+1)*PW - 1;
            float val = 0.f;
            if ((unsigned)yy < (unsigned)H && (unsigned)xx < (unsigned)W)
                val = in[(size_t)(n*IC + chunk + icp)*H*W + yy*W + xx];
            ins[i] = val;
        }
        __syncthreads();
        ull acc[2][9];
        #pragma unroll
        for (int pr = 0; pr < 2; pr++)
        #pragma unroll
        for (int k = 0; k < 9; k++) acc[pr][k] = 0ull;
        const float* myin = ins + icl*PHW;
        for (int y = lane; y < H; y += 32) {
            const float* r0p = myin + y*PW;
            const float* r1p = r0p + PW;
            const float* r2p = r1p + PW;
            const ull* d0y = ds2 + y*DW;
            const ull* d1y = ds2 + HDW + y*DW;
            float f;
            f = r0p[0]; ull pa0 = pk(f,f);
            f = r0p[1]; ull pa1 = pk(f,f);
            f = r1p[0]; ull pb0 = pk(f,f);
            f = r1p[1]; ull pb1 = pk(f,f);
            f = r2p[0]; ull pc0 = pk(f,f);
            f = r2p[1]; ull pc1 = pk(f,f);
            #pragma unroll 2
            for (int x = 0; x < W; x++) {
                float na = r0p[x+2], nb = r1p[x+2], nc = r2p[x+2];
                ull pa2 = pk(na,na), pb2 = pk(nb,nb), pc2 = pk(nc,nc);
                ull d0 = d0y[x], d1 = d1y[x];
                ffma2(acc[0][0], d0, pa0); ffma2(acc[0][1], d0, pa1); ffma2(acc[0][2], d0, pa2);
                ffma2(acc[0][3], d0, pb0); ffma2(acc[0][4], d0, pb1); ffma2(acc[0][5], d0, pb2);
                ffma2(acc[0][6], d0, pc0); ffma2(acc[0][7], d0, pc1); ffma2(acc[0][8], d0, pc2);
                ffma2(acc[1][0], d1, pa0); ffma2(acc[1][1], d1, pa1); ffma2(acc[1][2], d1, pa2);
                ffma2(acc[1][3], d1, pb0); ffma2(acc[1][4], d1, pb1); ffma2(acc[1][5], d1, pb2);
                ffma2(acc[1][6], d1, pc0); ffma2(acc[1][7], d1, pc1); ffma2(acc[1][8], d1, pc2);
                pa0 = pa1; pa1 = pa2; pb0 = pb1; pb1 = pb2; pc0 = pc1; pc1 = pc2;
            }
        }
        #pragma unroll
        for (int pr = 0; pr < 2; pr++)
        #pragma unroll
        for (int k = 0; k < 9; k++) {
            float v0, v1; upk(acc[pr][k], v0, v1);
            #pragma unroll
            for (int off = 16; off; off >>= 1) {
                v0 += __shfl_xor_sync(0xffffffffu, v0, off);
                v1 += __shfl_xor_sync(0xffffffffu, v1, off);
            }
            if (lane == 0) {
                size_t base = (size_t)n*F2 + gofs;
                G[base + ((size_t)(oc0+2*pr  )*IC + chunk + icl)*9 + k] = s*v0;
                G[base + ((size_t)(oc0+2*pr+1)*IC + chunk + icl)*9 + k] = s*v1;
            }
        }
    }
    __syncthreads();
    if (tid < 4) G[(size_t)n*F2 + bofs + oc0 + tid] = sb*bred[tid];
}

// layer-0 weight+bias gradient with fused unpool (no d0 buffer)
__global__ void wgrad0_k(const float* __restrict__ dp0, const unsigned char* __restrict__ i0,
                         const float* __restrict__ xp, float* __restrict__ G,
                         const float* __restrict__ scal)
{
    const int n = blockIdx.y, oh = blockIdx.x;
    extern __shared__ float sm[];
    float* ins  = sm;                 // 3*86*87
    float* ds   = ins + 22446;        // 84*85
    float* red  = ds + 7140;          // 3*9*84
    float* bred = red + 2268;         // 8
    const int tid = threadIdx.x;      // 256
    for (int i = tid; i < 3*86*87; i += 256) {
        int icp = i/(86*87), r = i - icp*(86*87);
        int yy = r/87 - 1, xx = r - (yy+1)*87 - 1;
        float val = 0.f;
        if ((unsigned)yy < 84u && (unsigned)xx < 84u)
            val = xp[(size_t)(n*3+icp)*7056 + yy*84 + xx];
        ins[i] = val;
    }
    const float s = scal[0], sb = scal[1];
    const int icl = tid / 84, rg = tid - icl*84;
    for (int oc8 = 0; oc8 < 32; oc8++) {
        const int oc = oh*32 + oc8;
        __syncthreads();
        const float* dpp = dp0 + (size_t)(n*64+oc)*1764;
        const unsigned char* ipp = i0 + (size_t)(n*64+oc)*1764;
        for (int i = tid; i < 84*85; i += 256) {
            int y = i/85, x = i - y*85;
            float val = 0.f;
            if (x < 84) {
                int py = y>>1, px = x>>1, j = ((y&1)<<1)|(x&1);
                int pi = py*42 + px;
                if (ipp[pi] == j) val = dpp[pi];
            }
            ds[i] = val;
        }
        __syncthreads();
        float bp = 0.f;
        for (int i = tid; i < 84*85; i += 256) bp += ds[i];
        #pragma unroll
        for (int off = 16; off; off >>= 1) bp += __shfl_xor_sync(0xffffffffu, bp, off);
        if ((tid & 31) == 0) bred[tid >> 5] = bp;
        float acc[9];
        #pragma unroll
        for (int k = 0; k < 9; k++) acc[k] = 0.f;
        if (tid < 252) {
            const float* r0p = ins + icl*7482 + rg*87;
            const float* r1p = r0p + 87;
            const float* r2p = r1p + 87;
            const float* dsy = ds + rg*85;
            float a0=r0p[0],a1=r0p[1],b0=r1p[0],b1=r1p[1],c0=r2p[0],c1=r2p[1];
            #pragma unroll 2
            for (int x = 0; x < 84; x++) {
                float a2=r0p[x+2], b2=r1p[x+2], c2=r2p[x+2];
                float d = dsy[x];
                acc[0]+=d*a0; acc[1]+=d*a1; acc[2]+=d*a2;
                acc[3]+=d*b0; acc[4]+=d*b1; acc[5]+=d*b2;
                acc[6]+=d*c0; acc[7]+=d*c1; acc[8]+=d*c2;
                a0=a1;a1=a2;b0=b1;b1=b2;c0=c1;c1=c2;
            }
            #pragma unroll
            for (int k = 0; k < 9; k++) red[(icl*9+k)*84 + rg] = acc[k];
        }
        __syncthreads();
        if (tid == 0) {
            float a = 0.f;
            #pragma unroll
            for (int wq = 0; wq < 8; wq++) a += bred[wq];
            G[(size_t)n*F2 + OB0 + oc] = sb*a;
        }
        for (int o = tid; o < 27; o += 256) {
            float t2 = 0.f;
            for (int r = 0; r < 84; r++) t2 += red[o*84 + r];
            int icg = o/9, uv = o - icg*9;
            G[(size_t)n*F2 + OW0 + (oc*3 + icg)*9 + uv] = s*t2;
        }
    }
}

__global__ void copyp3_k(const float* __restrict__ p3, float* __restrict__ G,
                         const float* __restrict__ scal)
{
    int t = blockIdx.x*256 + threadIdx.x;
    if (t >= 128*1600) return;
    int n = t / 1600, j = t - n*1600;
    G[(size_t)n*F2 + OFC + j] = scal[8]*p3[t];
}

// K partials: 128 split-F blocks, 4x4 register tiles over the 64x64 tile
__launch_bounds__(256)
__global__ void gemm2_k(const float* __restrict__ G, float* __restrict__ part)
{
    const int sp = blockIdx.x;
    const int f0 = sp*896;
    __shared__ float As[16][68], Bs[16][68];
    const int tid = threadIdx.x;
    const int row = tid >> 2, kq = tid & 3;
    const int ty = tid >> 4, tx = tid & 15;
    float acc[4][4];
    #pragma unroll
    for (int i = 0; i < 4; i++)
    #pragma unroll
    for (int j = 0; j < 4; j++) acc[i][j] = 0.f;
    const float* Ap = G + (size_t)row*F2 + f0 + kq*4;
    const float* Bp = G + (size_t)(64+row)*F2 + f0 + kq*4;
    #pragma unroll 1
    for (int fs = 0; fs < 56; fs++) {
        float4 a4 = *(const float4*)(Ap + fs*16);
        float4 b4 = *(const float4*)(Bp + fs*16);
        __syncthreads();
        As[kq*4+0][row] = a4.x; As[kq*4+1][row] = a4.y;
        As[kq*4+2][row] = a4.z; As[kq*4+3][row] = a4.w;
        Bs[kq*4+0][row] = b4.x; Bs[kq*4+1][row] = b4.y;
        Bs[kq*4+2][row] = b4.z; Bs[kq*4+3][row] = b4.w;
        __syncthreads();
        #pragma unroll
        for (int k = 0; k < 16; k++) {
            float4 av = *(const float4*)&As[k][ty*4];
            float4 bv = *(const float4*)&Bs[k][tx*4];
            float a[4] = {av.x, av.y, av.z, av.w};
            float b[4] = {bv.x, bv.y, bv.z, bv.w};
            #pragma unroll
            for (int i = 0; i < 4; i++)
            #pragma unroll
            for (int j = 0; j < 4; j++)
                acc[i][j] += a[i]*b[j];
        }
    }
    float* pp = part + (size_t)sp*4096;
    #pragma unroll
    for (int i = 0; i < 4; i++)
    #pragma unroll
    for (int j = 0; j < 4; j++)
        pp[(ty*4+i)*64 + (tx*4+j)] = acc[i][j];
}

__global__ void reduce_k(const float* __restrict__ part, const float* __restrict__ scal,
                         float* __restrict__ out)
{
    int t = blockIdx.x*256 + threadIdx.x;
    if (t >= 4096) return;
    float a = scal[9]*scal[9];
    #pragma unroll 8
    for (int sp = 0; sp < 128; sp++) a += part[sp*4096 + t];
    out[t] = a;
}

// ---------------- host ----------------
extern "C" void kernel_launch(void* const* d_in, const int* in_sizes, int n_in,
                              void* d_out, int out_size)
{
    const float* x1  = (const float*)d_in[0];
    const float* x2  = (const float*)d_in[1];
    const float* scal= (const float*)d_in[2];
    const int*   cp  = (const int*)  d_in[3];
    const float* w0  = (const float*)d_in[4];
    const float* b0  = (const float*)d_in[5];
    const float* w1  = (const float*)d_in[6];
    const float* b1  = (const float*)d_in[7];
    const float* w2  = (const float*)d_in[8];
    const float* b2  = (const float*)d_in[9];
    const float* w3  = (const float*)d_in[10];
    const float* b3  = (const float*)d_in[11];
    const float* fcw = (const float*)d_in[12];
    float* out = (float*)d_out;

    float *xp,*p0,*dp0,*p1,*dp1,*p2,*d3,*dp2,*p3,*wt,*G,*part;
    unsigned char *i0,*i1,*i2,*i3;
    cudaGetSymbolAddress((void**)&xp,  g_x);
    cudaGetSymbolAddress((void**)&p0,  g_p0);
    cudaGetSymbolAddress((void**)&dp0, g_dp0);
    cudaGetSymbolAddress((void**)&i0,  g_i0);
    cudaGetSymbolAddress((void**)&p1,  g_p1);
    cudaGetSymbolAddress((void**)&dp1, g_dp1);
    cudaGetSymbolAddress((void**)&i1,  g_i1);
    cudaGetSymbolAddress((void**)&p2,  g_p2);
    cudaGetSymbolAddress((void**)&d3,  g_d3);
    cudaGetSymbolAddress((void**)&dp2, g_dp2);
    cudaGetSymbolAddress((void**)&i2,  g_i2);
    cudaGetSymbolAddress((void**)&p3,  g_p3);
    cudaGetSymbolAddress((void**)&i3,  g_i3);
    cudaGetSymbolAddress((void**)&wt,  g_wt);
    cudaGetSymbolAddress((void**)&G,   g_G);
    cudaGetSymbolAddress((void**)&part,g_part);

    const int smW0 = (22446 + 7140 + 2268 + 8)*4;
    const int sm42 = (4*42*43)*4 + (8*44*45)*4 + 16;
    const int sm21 = (4*21*21)*4 + (8*23*23)*4 + 16;
    const int sm10 = (4*10*11)*4 + (8*12*13)*4 + 16;
    const int smC16 = 16*64*12*4;

    static cudaStream_t s1 = nullptr, s2 = nullptr;
    static cudaEvent_t eP3, eD3, eDp2, eDp1, eDp0, eS1, eS2;
    if (!s1) {
        cudaStreamCreateWithFlags(&s1, cudaStreamNonBlocking);
        cudaStreamCreateWithFlags(&s2, cudaStreamNonBlocking);
        cudaEventCreateWithFlags(&eP3,  cudaEventDisableTiming);
        cudaEventCreateWithFlags(&eD3,  cudaEventDisableTiming);
        cudaEventCreateWithFlags(&eDp2, cudaEventDisableTiming);
        cudaEventCreateWithFlags(&eDp1, cudaEventDisableTiming);
        cudaEventCreateWithFlags(&eDp0, cudaEventDisableTiming);
        cudaEventCreateWithFlags(&eS1,  cudaEventDisableTiming);
        cudaEventCreateWithFlags(&eS2,  cudaEventDisableTiming);
        cudaFuncSetAttribute(wgrad0_k, cudaFuncAttributeMaxDynamicSharedMemorySize, smW0);
        cudaFuncSetAttribute(wgrad2_k<64,8>, cudaFuncAttributeMaxDynamicSharedMemorySize, sm42);
        cudaFuncSetAttribute(convpool16_k, cudaFuncAttributeMaxDynamicSharedMemorySize, smC16);
        cudaFuncSetAttribute(conv2f_k<16>, cudaFuncAttributeMaxDynamicSharedMemorySize, smC16);
        cudaFuncSetAttribute(conv2f_k<8>,  cudaFuncAttributeMaxDynamicSharedMemorySize, 8*64*12*4);
    }
    const cudaStream_t m = 0;

    // ---- forward (main stream) ----
    pack_x_k<<<(128*3*84*84 + 255)/256, 256, 0, m>>>(x1, x2, xp);
    zpad_k<<<(128*(F2-F) + 255)/256, 256, 0, m>>>(G);
    convpool_k<3,1,1,true> <<<dim3(14,8,128),128,0,m>>>(xp, w0, b0, p0, i0, 84, 84, 42, 42);
    convpool16_k<<<dim3(4,4,128),128,smC16,m>>>(p0, w1, b1, p1, i1, 42, 42, 21, 21);
    convpool_k<64,1,1,false><<<dim3(1,8,128),128,0,m>>>(p1, w2, b2, p2, i2, 21, 21, 10, 10);
    convpool_k<64,5,25,true><<<dim3(1,8,26),128,0,m>>>(p2, w3, b3, p3, i3, 10, 10, 5, 5);
    cudaEventRecord(eP3, m);
    cudaStreamWaitEvent(s2, eP3, 0);
    copyp3_k<<<(128*1600 + 255)/256, 256, 0, s2>>>(p3, G, scal);
    cudaEventRecord(eS2, s2);

    // ---- backward chain (main); wgrads forked to s1 ----
    unpool_fc_k<<<(128*64*100 + 255)/256, 256, 0, m>>>(fcw, cp, i3, d3);
    transw_k<<<144,256,0,m>>>(w3, wt + 0*WTS);
    transw_k<<<144,256,0,m>>>(w2, wt + 1*WTS);
    transw_k<<<144,256,0,m>>>(w1, wt + 2*WTS);
    cudaEventRecord(eD3, m);
    cudaStreamWaitEvent(s1, eD3, 0);
    wgrad2_k<64,8><<<dim3(16,128), 256, sm10, s1>>>(d3, nullptr, p2, G, OW3, OB3, scal, 6, 10, 10, 5, 5);

    conv2_k<64,5,25><<<dim3(1,8,26),128,0,m>>>(d3, wt + 0*WTS, dp2, 10, 10);
    cudaEventRecord(eDp2, m);
    cudaStreamWaitEvent(s1, eDp2, 0);
    wgrad2_k<64,8><<<dim3(16,128), 256, sm21, s1>>>(dp2, i2, p1, G, OW2, OB2, scal, 4, 21, 21, 10, 10);

    conv2f_k<8><<<dim3(1,8,128),128, 8*64*12*4, m>>>(dp2, i2, wt + 1*WTS, dp1, 21, 21, 10, 10);
    cudaEventRecord(eDp1, m);
    cudaStreamWaitEvent(s1, eDp1, 0);
    wgrad2_k<64,8><<<dim3(16,128), 256, sm42, s1>>>(dp1, i1, p0, G, OW1, OB1, scal, 2, 42, 42, 21, 21);
    cudaEventRecord(eS1, s1);

    conv2f_k<16><<<dim3(4,4,128),128, smC16, m>>>(dp1, i1, wt + 2*WTS, dp0, 42, 42, 21, 21);

    // wgrad0 on main (it's the tail regardless)
    wgrad0_k<<<dim3(2,128), 256, smW0, m>>>(dp0, i0, xp, G, scal);

    // join and final GEMM
    cudaStreamWaitEvent(m, eS1, 0);
    cudaStreamWaitEvent(m, eS2, 0);
    gemm2_k<<<128, 256, 0, m>>>(G, part);
    reduce_k<<<16, 256, 0, m>>>(part, scal, out);
}

// round 15
// speedup vs baseline: 1.0821x; 1.0291x over previous
#include <cuda_runtime.h>

typedef unsigned long long ull;

__device__ __forceinline__ ull pk(float lo, float hi) {
    ull r; asm("mov.b64 %0,{%1,%2};" : "=l"(r) : "f"(lo), "f"(hi)); return r;
}
__device__ __forceinline__ void upk(ull v, float& lo, float& hi) {
    asm("mov.b64 {%0,%1},%2;" : "=f"(lo), "=f"(hi) : "l"(v));
}
__device__ __forceinline__ void ffma2(ull& d, ull a, ull b) {
    asm("fma.rn.f32x2 %0,%1,%2,%0;" : "+l"(d) : "l"(a), "l"(b));
}

// ---------------- constants ----------------
constexpr int F  = 114176;
constexpr int F2 = 114688;
constexpr int OW0 = 0, OB0 = 1728, OW1 = 1792, OB1 = 38656, OW2 = 38720,
              OB2 = 75584, OW3 = 75648, OB3 = 112512, OFC = 112576;
constexpr int WTS = 64*64*9;

// ---------------- scratch ----------------
__device__ float g_x  [128*3*84*84];
__device__ float g_p0 [128*64*42*42];
__device__ float g_dp0[128*64*42*42];
__device__ unsigned char g_i0[128*64*42*42];
__device__ float g_p1 [128*64*21*21];
__device__ float g_dp1[128*64*21*21];
__device__ unsigned char g_i1[128*64*21*21];
__device__ float g_p2 [128*64*10*10];
__device__ float g_d3 [128*64*10*10];
__device__ float g_dp2[128*64*10*10];
__device__ unsigned char g_i2[128*64*10*10];
__device__ float g_p3 [128*64*5*5];
__device__ unsigned char g_i3[128*64*5*5];
__device__ float g_wt [3*WTS];
__device__ float g_G  [128*(size_t)F2];
__device__ float g_part[128*4096];

// ---------------- kernels ----------------
__global__ void packh_k(const float* __restrict__ src, float* __restrict__ dst) {
    int t = blockIdx.x*256 + threadIdx.x;
    if (t >= 64*3*84*84) return;
    dst[t] = src[t];
}

__global__ void zpad_k(float* __restrict__ G) {
    int t = blockIdx.x*256 + threadIdx.x;
    if (t >= 128*(F2-F)) return;
    int n = t >> 9, j = t & 511;
    G[(size_t)n*F2 + F + j] = 0.f;
}

// fused conv3x3(SAME)+bias+relu+2x2 maxpool; 8 oc x 4 px register tiles
template<int IC, int NPB, int PXT, bool VEC>
__launch_bounds__(128)
__global__ void convpool_k(const float* __restrict__ in, const float* __restrict__ w,
                           const float* __restrict__ bias, float* __restrict__ p,
                           unsigned char* __restrict__ idx,
                           int H, int W, int Hp, int Wp, int nb)
{
    const int oc0 = blockIdx.y*8;
    __shared__ float ws[8*IC*12];
    __shared__ float bs[8];
    for (int i = threadIdx.x; i < 8*IC*9; i += 128) {
        int oi = i/9, k = i - oi*9;
        ws[oi*12+k] = w[(size_t)oc0*IC*9 + i];
    }
    if (threadIdx.x < 8) bs[threadIdx.x] = bias[oc0+threadIdx.x];
    __syncthreads();
    int n, t;
    if (NPB == 1) {
        n = nb + blockIdx.z; t = blockIdx.x*128 + threadIdx.x;
        if (t >= Hp*Wp) return;
    } else {
        int q = threadIdx.x / PXT; t = threadIdx.x - q*PXT;
        n = nb + blockIdx.z*NPB + q;
        if (q >= NPB || n >= nb + 64) return;
    }
    int py = t / Wp, px = t - py*Wp;
    int y0 = py*2, x0 = px*2;
    bool rv[4];
    #pragma unroll
    for (int u = 0; u < 4; u++) { int yy = y0-1+u; rv[u] = (unsigned)yy < (unsigned)H; }
    const bool ax = (x0 >= 2);
    const bool cx = (x0 + 2 < W);
    int offs[4][4];
    if (!VEC) {
        #pragma unroll
        for (int u = 0; u < 4; u++)
        #pragma unroll
        for (int j = 0; j < 4; j++) {
            int xx = x0-1+j;
            offs[u][j] = (rv[u] && (unsigned)xx < (unsigned)W) ? (y0-1+u)*W+xx : -1;
        }
    }
    float acc[8][4];
    #pragma unroll
    for (int o = 0; o < 8; o++) {
        float b = bs[o];
        acc[o][0]=b; acc[o][1]=b; acc[o][2]=b; acc[o][3]=b;
    }
    const int HW = H*W;
    const float* ip = in + (size_t)n*IC*HW;
    const float* bp = ip + (y0-1)*W + x0;
    #pragma unroll 1
    for (int ic = 0; ic < IC; ic++, ip += HW, bp += HW) {
        float v[4][4];
        if (VEC) {
            #pragma unroll
            for (int u = 0; u < 4; u++) {
                const float* rp = bp + u*W;
                float2 A = (rv[u] && ax) ? *(const float2*)(rp - 2) : make_float2(0.f, 0.f);
                float2 B =  rv[u]        ? *(const float2*)(rp    ) : make_float2(0.f, 0.f);
                float2 C = (rv[u] && cx) ? *(const float2*)(rp + 2) : make_float2(0.f, 0.f);
                v[u][0] = A.y; v[u][1] = B.x; v[u][2] = B.y; v[u][3] = C.x;
            }
        } else {
            #pragma unroll
            for (int u = 0; u < 4; u++)
            #pragma unroll
            for (int j = 0; j < 4; j++)
                v[u][j] = (offs[u][j] >= 0) ? ip[offs[u][j]] : 0.0f;
        }
        #pragma unroll
        for (int o = 0; o < 8; o++) {
            float wr[12];
            *(float4*)&wr[0] = *(const float4*)&ws[(o*IC+ic)*12];
            *(float4*)&wr[4] = *(const float4*)&ws[(o*IC+ic)*12+4];
            wr[8] = ws[(o*IC+ic)*12+8];
            #pragma unroll
            for (int u = 0; u < 3; u++)
            #pragma unroll
            for (int vv = 0; vv < 3; vv++) {
                float wv = wr[u*3+vv];
                acc[o][0] += wv*v[u  ][vv  ];
                acc[o][1] += wv*v[u  ][vv+1];
                acc[o][2] += wv*v[u+1][vv  ];
                acc[o][3] += wv*v[u+1][vv+1];
            }
        }
    }
    #pragma unroll
    for (int o = 0; o < 8; o++) {
        float a0 = fmaxf(acc[o][0],0.f), a1 = fmaxf(acc[o][1],0.f),
              a2 = fmaxf(acc[o][2],0.f), a3 = fmaxf(acc[o][3],0.f);
        float m = a0; int am = 0;
        if (a1 > m) { m = a1; am = 1; }
        if (a2 > m) { m = a2; am = 2; }
        if (a3 > m) { m = a3; am = 3; }
        size_t ob = ((size_t)(n*64+oc0+o)*Hp + py)*Wp + px;
        p[ob] = m;
        idx[ob] = (m > 0.f) ? (unsigned char)am : (unsigned char)4;
    }
}

// 16 oc x 4 px fused conv+bias+relu+pool, IC=64, VEC (42x42 layer)
__launch_bounds__(128)
__global__ void convpool16_k(const float* __restrict__ in, const float* __restrict__ w,
                             const float* __restrict__ bias, float* __restrict__ p,
                             unsigned char* __restrict__ idx,
                             int H, int W, int Hp, int Wp, int nb)
{
    const int oc0 = blockIdx.y*16;
    extern __shared__ float ws[];
    __shared__ float bs[16];
    for (int i = threadIdx.x; i < 16*64*9; i += 128) {
        int oi = i/9, k = i - oi*9;
        ws[oi*12+k] = w[(size_t)oc0*64*9 + i];
    }
    if (threadIdx.x < 16) bs[threadIdx.x] = bias[oc0+threadIdx.x];
    __syncthreads();
    const int n = nb + blockIdx.z;
    int t = blockIdx.x*128 + threadIdx.x;
    if (t >= Hp*Wp) return;
    int py = t / Wp, px = t - py*Wp;
    int y0 = py*2, x0 = px*2;
    bool rv[4];
    #pragma unroll
    for (int u = 0; u < 4; u++) { int yy = y0-1+u; rv[u] = (unsigned)yy < (unsigned)H; }
    const bool ax = (x0 >= 2);
    const bool cx = (x0 + 2 < W);
    float acc[16][4];
    #pragma unroll
    for (int o = 0; o < 16; o++) {
        float b = bs[o];
        acc[o][0]=b; acc[o][1]=b; acc[o][2]=b; acc[o][3]=b;
    }
    const int HW = H*W;
    const float* bp = in + (size_t)n*64*HW + (y0-1)*W + x0;
    #pragma unroll 1
    for (int ic = 0; ic < 64; ic++, bp += HW) {
        float v[4][4];
        #pragma unroll
        for (int u = 0; u < 4; u++) {
            const float* rp = bp + u*W;
            float2 A = (rv[u] && ax) ? *(const float2*)(rp - 2) : make_float2(0.f, 0.f);
            float2 B =  rv[u]        ? *(const float2*)(rp    ) : make_float2(0.f, 0.f);
            float2 C = (rv[u] && cx) ? *(const float2*)(rp + 2) : make_float2(0.f, 0.f);
            v[u][0] = A.y; v[u][1] = B.x; v[u][2] = B.y; v[u][3] = C.x;
        }
        #pragma unroll
        for (int o = 0; o < 16; o++) {
            float wr[12];
            *(float4*)&wr[0] = *(const float4*)&ws[(o*64+ic)*12];
            *(float4*)&wr[4] = *(const float4*)&ws[(o*64+ic)*12+4];
            wr[8] = ws[(o*64+ic)*12+8];
            #pragma unroll
            for (int u = 0; u < 3; u++)
            #pragma unroll
            for (int vv = 0; vv < 3; vv++) {
                float wv = wr[u*3+vv];
                acc[o][0] += wv*v[u  ][vv  ];
                acc[o][1] += wv*v[u  ][vv+1];
                acc[o][2] += wv*v[u+1][vv  ];
                acc[o][3] += wv*v[u+1][vv+1];
            }
        }
    }
    #pragma unroll
    for (int o = 0; o < 16; o++) {
        float a0 = fmaxf(acc[o][0],0.f), a1 = fmaxf(acc[o][1],0.f),
              a2 = fmaxf(acc[o][2],0.f), a3 = fmaxf(acc[o][3],0.f);
        float m = a0; int am = 0;
        if (a1 > m) { m = a1; am = 1; }
        if (a2 > m) { m = a2; am = 2; }
        if (a3 > m) { m = a3; am = 3; }
        size_t ob = ((size_t)(n*64+oc0+o)*Hp + py)*Wp + px;
        p[ob] = m;
        idx[ob] = (m > 0.f) ? (unsigned char)am : (unsigned char)4;
    }
}

// plain backward-data conv (10x10 layer only), 8 oc
template<int IC, int NPB, int PXT>
__launch_bounds__(128)
__global__ void conv2_k(const float* __restrict__ in, const float* __restrict__ w,
                        float* __restrict__ out, int H, int W, int nb)
{
    const int oc0 = blockIdx.y*8;
    const int TW = (W+1) >> 1;
    __shared__ float ws[8*IC*12];
    for (int i = threadIdx.x; i < 8*IC*9; i += 128) {
        int oi = i/9, k = i - oi*9;
        ws[oi*12+k] = w[(size_t)oc0*IC*9 + i];
    }
    __syncthreads();
    int q = threadIdx.x / PXT, t = threadIdx.x - q*PXT;
    int n = nb + blockIdx.z*NPB + q;
    if (q >= NPB || n >= nb + 64) return;
    int ty = t / TW, tx = t - ty*TW;
    int y0 = ty*2, x0 = tx*2;
    int offs[4][4];
    #pragma unroll
    for (int u = 0; u < 4; u++) {
        int yy = y0-1+u; bool rv = (unsigned)yy < (unsigned)H;
        #pragma unroll
        for (int j = 0; j < 4; j++) {
            int xx = x0-1+j;
            offs[u][j] = (rv && (unsigned)xx < (unsigned)W) ? yy*W+xx : -1;
        }
    }
    float acc[8][4];
    #pragma unroll
    for (int o = 0; o < 8; o++) { acc[o][0]=0.f; acc[o][1]=0.f; acc[o][2]=0.f; acc[o][3]=0.f; }
    const float* ip = in + (size_t)n*IC*H*W;
    #pragma unroll 1
    for (int ic = 0; ic < IC; ic++, ip += H*W) {
        float v[4][4];
        #pragma unroll
        for (int u = 0; u < 4; u++)
        #pragma unroll
        for (int j = 0; j < 4; j++)
            v[u][j] = (offs[u][j] >= 0) ? ip[offs[u][j]] : 0.0f;
        #pragma unroll
        for (int o = 0; o < 8; o++) {
            float wr[12];
            *(float4*)&wr[0] = *(const float4*)&ws[(o*IC+ic)*12];
            *(float4*)&wr[4] = *(const float4*)&ws[(o*IC+ic)*12+4];
            wr[8] = ws[(o*IC+ic)*12+8];
            #pragma unroll
            for (int u = 0; u < 3; u++)
            #pragma unroll
            for (int vv = 0; vv < 3; vv++) {
                float wv = wr[u*3+vv];
                acc[o][0] += wv*v[u  ][vv  ];
                acc[o][1] += wv*v[u  ][vv+1];
                acc[o][2] += wv*v[u+1][vv  ];
                acc[o][3] += wv*v[u+1][vv+1];
            }
        }
    }
    bool xv = (x0+1 < W), yv = (y0+1 < H);
    #pragma unroll
    for (int o = 0; o < 8; o++) {
        float* op = out + ((size_t)(n*64+oc0+o)*H + y0)*W + x0;
        op[0] = acc[o][0];
        if (xv) op[1] = acc[o][1];
        if (yv) { op[W] = acc[o][2]; if (xv) op[W+1] = acc[o][3]; }
    }
}

// backward-data conv with FUSED unpool, OCG oc x 4 px
template<int OCG>
__launch_bounds__(128)
__global__ void conv2f_k(const float* __restrict__ dp, const unsigned char* __restrict__ ib,
                         const float* __restrict__ w, float* __restrict__ out,
                         int H, int W, int Hp, int Wp, int nb)
{
    const int n = nb + blockIdx.z, oc0 = blockIdx.y*OCG;
    const int TW = (W+1) >> 1, TH = (H+1) >> 1;
    extern __shared__ float ws[];
    for (int i = threadIdx.x; i < OCG*64*9; i += 128) {
        int oi = i/9, k = i - oi*9;
        ws[oi*12+k] = w[(size_t)oc0*64*9 + i];
    }
    __syncthreads();
    int t = blockIdx.x*128 + threadIdx.x;
    if (t >= TH*TW) return;
    int ty = t / TW, tx = t - ty*TW;
    int poff[3][3];
    #pragma unroll
    for (int a = 0; a < 3; a++) {
        int py = ty - 1 + a; bool rv = (unsigned)py < (unsigned)Hp;
        #pragma unroll
        for (int b = 0; b < 3; b++) {
            int px = tx - 1 + b;
            poff[a][b] = (rv && (unsigned)px < (unsigned)Wp) ? py*Wp+px : -1;
        }
    }
    const int AY[4] = {0,1,1,2};
    const int QY[4] = {1,0,1,0};
    float acc[OCG][4];
    #pragma unroll
    for (int o = 0; o < OCG; o++) { acc[o][0]=0.f; acc[o][1]=0.f; acc[o][2]=0.f; acc[o][3]=0.f; }
    const int PS = Hp*Wp;
    const float* dpp = dp + (size_t)n*64*PS;
    const unsigned char* ibp = ib + (size_t)n*64*PS;
    #pragma unroll 1
    for (int ic = 0; ic < 64; ic++, dpp += PS, ibp += PS) {
        float d[3][3]; int id[3][3];
        #pragma unroll
        for (int a = 0; a < 3; a++)
        #pragma unroll
        for (int b = 0; b < 3; b++) {
            int o2 = poff[a][b];
            bool v2 = (o2 >= 0);
            d[a][b]  = v2 ? dpp[o2] : 0.f;
            id[a][b] = v2 ? (int)ibp[o2] : 4;
        }
        float v[4][4];
        #pragma unroll
        for (int u = 0; u < 4; u++)
        #pragma unroll
        for (int j = 0; j < 4; j++) {
            int a = AY[u], b = AY[j];
            int qq = QY[u]*2 + QY[j];
            v[u][j] = (id[a][b] == qq) ? d[a][b] : 0.f;
        }
        #pragma unroll
        for (int o = 0; o < OCG; o++) {
            float wr[12];
            *(float4*)&wr[0] = *(const float4*)&ws[(o*64+ic)*12];
            *(float4*)&wr[4] = *(const float4*)&ws[(o*64+ic)*12+4];
            wr[8] = ws[(o*64+ic)*12+8];
            #pragma unroll
            for (int u = 0; u < 3; u++)
            #pragma unroll
            for (int vv = 0; vv < 3; vv++) {
                float wv = wr[u*3+vv];
                acc[o][0] += wv*v[u  ][vv  ];
                acc[o][1] += wv*v[u  ][vv+1];
                acc[o][2] += wv*v[u+1][vv  ];
                acc[o][3] += wv*v[u+1][vv+1];
            }
        }
    }
    int y0 = 2*ty, x0 = 2*tx;
    bool xv = (x0+1 < W), yv = (y0+1 < H);
    #pragma unroll
    for (int o = 0; o < OCG; o++) {
        float* op = out + ((size_t)(n*64+oc0+o)*H + y0)*W + x0;
        op[0] = acc[o][0];
        if (xv) op[1] = acc[o][1];
        if (yv) { op[W] = acc[o][2]; if (xv) op[W+1] = acc[o][3]; }
    }
}

__global__ void unpool_fc_k(const float* __restrict__ fcw, const int* __restrict__ cptr,
                            const unsigned char* __restrict__ idx, float* __restrict__ delta,
                            int nb)
{
    int t = blockIdx.x*256 + threadIdx.x;
    if (t >= 64*64*100) return;
    int x = t % 10, y = (t / 10) % 10, ch = (t / 100) % 64, n = nb + t / 6400;
    int py = y >> 1, px = x >> 1, j = ((y & 1) << 1) | (x & 1);
    int pi = ((n*64 + ch)*5 + py)*5 + px;
    float val = 0.0f;
    if (idx[pi] == j) {
        int cc = cptr[0];
        val = fcw[cc*1600 + ch*25 + py*5 + px];
    }
    delta[((size_t)n*64 + ch)*100 + y*10 + x] = val;
}

__global__ void transw_k(const float* __restrict__ w, float* __restrict__ wt) {
    int t = blockIdx.x*256 + threadIdx.x;
    if (t >= 64*64*9) return;
    int uv = t % 9, ic = (t / 9) % 64, oc = t / 576;
    int u = uv / 3, v = uv % 3;
    wt[(ic*64 + oc)*9 + (2-u)*3 + (2-v)] = w[t];
}

// weight+bias gradient, layers 1..3, packed f32x2 over oc-pairs.
template<int IC, int ICC>
__global__ void wgrad2_k(const float* __restrict__ dp, const unsigned char* __restrict__ ib,
                         const float* __restrict__ in,
                         float* __restrict__ G, int gofs, int bofs,
                         const float* __restrict__ scal, int sidx, int H, int W,
                         int Hp, int Wp, int nb)
{
    const int n = nb + blockIdx.y, oc0 = blockIdx.x*4;
    const int DW = W | 1;
    const int PW = (W+2) | 1;
    const int PH = H + 2;
    const int HDW = H*DW, PHW = PH*PW;
    extern __shared__ float sm[];
    ull*   ds2  = (ull*)sm;
    float* ins  = sm + 4*HDW;
    float* bred = ins + ICC*PHW;
    const int tid = threadIdx.x;
    const int lane = tid & 31, icl = tid >> 5;
    const int NT = ICC*32;
    if (tid < 4) bred[tid] = 0.f;
    for (int i = tid; i < 2*HDW; i += NT) {
        int pr = i / HDW, r = i - pr*HDW;
        int y = r / DW, x = r - y*DW;
        float lo = 0.f, hi = 0.f;
        if (x < W) {
            int plane0 = n*64 + oc0 + 2*pr;
            if (ib) {
                if (y < 2*Hp && x < 2*Wp) {
                    int py = y>>1, px = x>>1, j = ((y&1)<<1)|(x&1);
                    size_t pi0 = ((size_t)plane0*Hp + py)*Wp + px;
                    size_t pi1 = pi0 + (size_t)Hp*Wp;
                    if (ib[pi0] == j) lo = dp[pi0];
                    if (ib[pi1] == j) hi = dp[pi1];
                }
            } else {
                size_t b = (size_t)plane0*H*W + y*W + x;
                lo = dp[b]; hi = dp[b + (size_t)H*W];
            }
        }
        ds2[i] = pk(lo, hi);
    }
    __syncthreads();
    #pragma unroll
    for (int pr = 0; pr < 2; pr++) {
        float s0 = 0.f, s1 = 0.f;
        for (int i = tid; i < HDW; i += NT) {
            float lo, hi; upk(ds2[pr*HDW + i], lo, hi);
            s0 += lo; s1 += hi;
        }
        #pragma unroll
        for (int off = 16; off; off >>= 1) {
            s0 += __shfl_xor_sync(0xffffffffu, s0, off);
            s1 += __shfl_xor_sync(0xffffffffu, s1, off);
        }
        if (lane == 0) { atomicAdd(&bred[2*pr], s0); atomicAdd(&bred[2*pr+1], s1); }
    }
    const float s  = scal[sidx];
    const float sb = scal[sidx+1];
    for (int chunk = 0; chunk < IC; chunk += ICC) {
        __syncthreads();
        for (int i = tid; i < ICC*PHW; i += NT) {
            int icp = i / PHW, r = i - icp*PHW;
            int yy = r / PW - 1, xx = r - (yy+1)*PW - 1;
            float val = 0.f;
            if ((unsigned)yy < (unsigned)H && (unsigned)xx < (unsigned)W)
                val = in[(size_t)(n*IC + chunk + icp)*H*W + yy*W + xx];
            ins[i] = val;
        }
        __syncthreads();
        ull acc[2][9];
        #pragma unroll
        for (int pr = 0; pr < 2; pr++)
        #pragma unroll
        for (int k = 0; k < 9; k++) acc[pr][k] = 0ull;
        const float* myin = ins + icl*PHW;
        for (int y = lane; y < H; y += 32) {
            const float* r0p = myin + y*PW;
            const float* r1p = r0p + PW;
            const float* r2p = r1p + PW;
            const ull* d0y = ds2 + y*DW;
            const ull* d1y = ds2 + HDW + y*DW;
            float f;
            f = r0p[0]; ull pa0 = pk(f,f);
            f = r0p[1]; ull pa1 = pk(f,f);
            f = r1p[0]; ull pb0 = pk(f,f);
            f = r1p[1]; ull pb1 = pk(f,f);
            f = r2p[0]; ull pc0 = pk(f,f);
            f = r2p[1]; ull pc1 = pk(f,f);
            #pragma unroll 2
            for (int x = 0; x < W; x++) {
                float na = r0p[x+2], nb2 = r1p[x+2], nc = r2p[x+2];
                ull pa2 = pk(na,na), pb2 = pk(nb2,nb2), pc2 = pk(nc,nc);
                ull d0 = d0y[x], d1 = d1y[x];
                ffma2(acc[0][0], d0, pa0); ffma2(acc[0][1], d0, pa1); ffma2(acc[0][2], d0, pa2);
                ffma2(acc[0][3], d0, pb0); ffma2(acc[0][4], d0, pb1); ffma2(acc[0][5], d0, pb2);
                ffma2(acc[0][6], d0, pc0); ffma2(acc[0][7], d0, pc1); ffma2(acc[0][8], d0, pc2);
                ffma2(acc[1][0], d1, pa0); ffma2(acc[1][1], d1, pa1); ffma2(acc[1][2], d1, pa2);
                ffma2(acc[1][3], d1, pb0); ffma2(acc[1][4], d1, pb1); ffma2(acc[1][5], d1, pb2);
                ffma2(acc[1][6], d1, pc0); ffma2(acc[1][7], d1, pc1); ffma2(acc[1][8], d1, pc2);
                pa0 = pa1; pa1 = pa2; pb0 = pb1; pb1 = pb2; pc0 = pc1; pc1 = pc2;
            }
        }
        #pragma unroll
        for (int pr = 0; pr < 2; pr++)
        #pragma unroll
        for (int k = 0; k < 9; k++) {
            float v0, v1; upk(acc[pr][k], v0, v1);
            #pragma unroll
            for (int off = 16; off; off >>= 1) {
                v0 += __shfl_xor_sync(0xffffffffu, v0, off);
                v1 += __shfl_xor_sync(0xffffffffu, v1, off);
            }
            if (lane == 0) {
                size_t base = (size_t)n*F2 + gofs;
                G[base + ((size_t)(oc0+2*pr  )*IC + chunk + icl)*9 + k] = s*v0;
                G[base + ((size_t)(oc0+2*pr+1)*IC + chunk + icl)*9 + k] = s*v1;
            }
        }
    }
    __syncthreads();
    if (tid < 4) G[(size_t)n*F2 + bofs + oc0 + tid] = sb*bred[tid];
}

// layer-0 weight+bias gradient with fused unpool (no d0 buffer)
__global__ void wgrad0_k(const float* __restrict__ dp0, const unsigned char* __restrict__ i0,
                         const float* __restrict__ xp, float* __restrict__ G,
                         const float* __restrict__ scal, int nb)
{
    const int n = nb + blockIdx.y, oh = blockIdx.x;
    extern __shared__ float sm[];
    float* ins  = sm;
    float* ds   = ins + 22446;
    float* red  = ds + 7140;
    float* bred = red + 2268;
    const int tid = threadIdx.x;
    for (int i = tid; i < 3*86*87; i += 256) {
        int icp = i/(86*87), r = i - icp*(86*87);
        int yy = r/87 - 1, xx = r - (yy+1)*87 - 1;
        float val = 0.f;
        if ((unsigned)yy < 84u && (unsigned)xx < 84u)
            val = xp[(size_t)(n*3+icp)*7056 + yy*84 + xx];
        ins[i] = val;
    }
    const float s = scal[0], sb = scal[1];
    const int icl = tid / 84, rg = tid - icl*84;
    for (int oc8 = 0; oc8 < 32; oc8++) {
        const int oc = oh*32 + oc8;
        __syncthreads();
        const float* dpp = dp0 + (size_t)(n*64+oc)*1764;
        const unsigned char* ipp = i0 + (size_t)(n*64+oc)*1764;
        for (int i = tid; i < 84*85; i += 256) {
            int y = i/85, x = i - y*85;
            float val = 0.f;
            if (x < 84) {
                int py = y>>1, px = x>>1, j = ((y&1)<<1)|(x&1);
                int pi = py*42 + px;
                if (ipp[pi] == j) val = dpp[pi];
            }
            ds[i] = val;
        }
        __syncthreads();
        float bp = 0.f;
        for (int i = tid; i < 84*85; i += 256) bp += ds[i];
        #pragma unroll
        for (int off = 16; off; off >>= 1) bp += __shfl_xor_sync(0xffffffffu, bp, off);
        if ((tid & 31) == 0) bred[tid >> 5] = bp;
        float acc[9];
        #pragma unroll
        for (int k = 0; k < 9; k++) acc[k] = 0.f;
        if (tid < 252) {
            const float* r0p = ins + icl*7482 + rg*87;
            const float* r1p = r0p + 87;
            const float* r2p = r1p + 87;
            const float* dsy = ds + rg*85;
            float a0=r0p[0],a1=r0p[1],b0=r1p[0],b1=r1p[1],c0=r2p[0],c1=r2p[1];
            #pragma unroll 2
            for (int x = 0; x < 84; x++) {
                float a2=r0p[x+2], b2=r1p[x+2], c2=r2p[x+2];
                float d = dsy[x];
                acc[0]+=d*a0; acc[1]+=d*a1; acc[2]+=d*a2;
                acc[3]+=d*b0; acc[4]+=d*b1; acc[5]+=d*b2;
                acc[6]+=d*c0; acc[7]+=d*c1; acc[8]+=d*c2;
                a0=a1;a1=a2;b0=b1;b1=b2;c0=c1;c1=c2;
            }
            #pragma unroll
            for (int k = 0; k < 9; k++) red[(icl*9+k)*84 + rg] = acc[k];
        }
        __syncthreads();
        if (tid == 0) {
            float a = 0.f;
            #pragma unroll
            for (int wq = 0; wq < 8; wq++) a += bred[wq];
            G[(size_t)n*F2 + OB0 + oc] = sb*a;
        }
        for (int o = tid; o < 27; o += 256) {
            float t2 = 0.f;
            for (int r = 0; r < 84; r++) t2 += red[o*84 + r];
            int icg = o/9, uv = o - icg*9;
            G[(size_t)n*F2 + OW0 + (oc*3 + icg)*9 + uv] = s*t2;
        }
    }
}

__global__ void copyp3_k(const float* __restrict__ p3, float* __restrict__ G,
                         const float* __restrict__ scal, int nb)
{
    int t = blockIdx.x*256 + threadIdx.x;
    if (t >= 64*1600) return;
    int n = nb + t / 1600, j = t % 1600;
    G[(size_t)n*F2 + OFC + j] = scal[8]*p3[(size_t)n*1600 + j];
}

// K partials: 128 split-F blocks, 4x4 register tiles over the 64x64 tile
__launch_bounds__(256)
__global__ void gemm2_k(const float* __restrict__ G, float* __restrict__ part)
{
    const int sp = blockIdx.x;
    const int f0 = sp*896;
    __shared__ float As[16][68], Bs[16][68];
    const int tid = threadIdx.x;
    const int row = tid >> 2, kq = tid & 3;
    const int ty = tid >> 4, tx = tid & 15;
    float acc[4][4];
    #pragma unroll
    for (int i = 0; i < 4; i++)
    #pragma unroll
    for (int j = 0; j < 4; j++) acc[i][j] = 0.f;
    const float* Ap = G + (size_t)row*F2 + f0 + kq*4;
    const float* Bp = G + (size_t)(64+row)*F2 + f0 + kq*4;
    #pragma unroll 1
    for (int fs = 0; fs < 56; fs++) {
        float4 a4 = *(const float4*)(Ap + fs*16);
        float4 b4 = *(const float4*)(Bp + fs*16);
        __syncthreads();
        As[kq*4+0][row] = a4.x; As[kq*4+1][row] = a4.y;
        As[kq*4+2][row] = a4.z; As[kq*4+3][row] = a4.w;
        Bs[kq*4+0][row] = b4.x; Bs[kq*4+1][row] = b4.y;
        Bs[kq*4+2][row] = b4.z; Bs[kq*4+3][row] = b4.w;
        __syncthreads();
        #pragma unroll
        for (int k = 0; k < 16; k++) {
            float4 av = *(const float4*)&As[k][ty*4];
            float4 bv = *(const float4*)&Bs[k][tx*4];
            float a[4] = {av.x, av.y, av.z, av.w};
            float b[4] = {bv.x, bv.y, bv.z, bv.w};
            #pragma unroll
            for (int i = 0; i < 4; i++)
            #pragma unroll
            for (int j = 0; j < 4; j++)
                acc[i][j] += a[i]*b[j];
        }
    }
    float* pp = part + (size_t)sp*4096;
    #pragma unroll
    for (int i = 0; i < 4; i++)
    #pragma unroll
    for (int j = 0; j < 4; j++)
        pp[(ty*4+i)*64 + (tx*4+j)] = acc[i][j];
}

__global__ void reduce_k(const float* __restrict__ part, const float* __restrict__ scal,
                         float* __restrict__ out)
{
    int t = blockIdx.x*256 + threadIdx.x;
    if (t >= 4096) return;
    float a = scal[9]*scal[9];
    #pragma unroll 8
    for (int sp = 0; sp < 128; sp++) a += part[sp*4096 + t];
    out[t] = a;
}

// ---------------- host ----------------
extern "C" void kernel_launch(void* const* d_in, const int* in_sizes, int n_in,
                              void* d_out, int out_size)
{
    const float* x1  = (const float*)d_in[0];
    const float* x2  = (const float*)d_in[1];
    const float* scal= (const float*)d_in[2];
    const int*   cp  = (const int*)  d_in[3];
    const float* w0  = (const float*)d_in[4];
    const float* b0  = (const float*)d_in[5];
    const float* w1  = (const float*)d_in[6];
    const float* b1  = (const float*)d_in[7];
    const float* w2  = (const float*)d_in[8];
    const float* b2  = (const float*)d_in[9];
    const float* w3  = (const float*)d_in[10];
    const float* b3  = (const float*)d_in[11];
    const float* fcw = (const float*)d_in[12];
    float* out = (float*)d_out;

    float *xp,*p0,*dp0,*p1,*dp1,*p2,*d3,*dp2,*p3,*wt,*G,*part;
    unsigned char *i0,*i1,*i2,*i3;
    cudaGetSymbolAddress((void**)&xp,  g_x);
    cudaGetSymbolAddress((void**)&p0,  g_p0);
    cudaGetSymbolAddress((void**)&dp0, g_dp0);
    cudaGetSymbolAddress((void**)&i0,  g_i0);
    cudaGetSymbolAddress((void**)&p1,  g_p1);
    cudaGetSymbolAddress((void**)&dp1, g_dp1);
    cudaGetSymbolAddress((void**)&i1,  g_i1);
    cudaGetSymbolAddress((void**)&p2,  g_p2);
    cudaGetSymbolAddress((void**)&d3,  g_d3);
    cudaGetSymbolAddress((void**)&dp2, g_dp2);
    cudaGetSymbolAddress((void**)&i2,  g_i2);
    cudaGetSymbolAddress((void**)&p3,  g_p3);
    cudaGetSymbolAddress((void**)&i3,  g_i3);
    cudaGetSymbolAddress((void**)&wt,  g_wt);
    cudaGetSymbolAddress((void**)&G,   g_G);
    cudaGetSymbolAddress((void**)&part,g_part);

    const int smW0 = (22446 + 7140 + 2268 + 8)*4;
    const int sm42 = (4*42*43)*4 + (8*44*45)*4 + 16;
    const int sm21 = (4*21*21)*4 + (8*23*23)*4 + 16;
    const int sm10 = (4*10*11)*4 + (8*12*13)*4 + 16;
    const int smC16 = 16*64*12*4;

    static cudaStream_t s1 = nullptr, s2 = nullptr;
    static cudaEvent_t eFork, eWt, eB, eZ;
    if (!s1) {
        cudaStreamCreateWithFlags(&s1, cudaStreamNonBlocking);
        cudaStreamCreateWithFlags(&s2, cudaStreamNonBlocking);
        cudaEventCreateWithFlags(&eFork, cudaEventDisableTiming);
        cudaEventCreateWithFlags(&eWt, cudaEventDisableTiming);
        cudaEventCreateWithFlags(&eB,  cudaEventDisableTiming);
        cudaEventCreateWithFlags(&eZ,  cudaEventDisableTiming);
        cudaFuncSetAttribute(wgrad0_k, cudaFuncAttributeMaxDynamicSharedMemorySize, smW0);
        cudaFuncSetAttribute(wgrad2_k<64,8>, cudaFuncAttributeMaxDynamicSharedMemorySize, sm42);
        cudaFuncSetAttribute(convpool16_k, cudaFuncAttributeMaxDynamicSharedMemorySize, smC16);
        cudaFuncSetAttribute(conv2f_k<16>, cudaFuncAttributeMaxDynamicSharedMemorySize, smC16);
        cudaFuncSetAttribute(conv2f_k<8>,  cudaFuncAttributeMaxDynamicSharedMemorySize, 8*64*12*4);
    }
    const cudaStream_t m = 0;

    // fork from the capture-origin stream FIRST (required for graph capture)
    cudaEventRecord(eFork, m);
    cudaStreamWaitEvent(s1, eFork, 0);
    cudaStreamWaitEvent(s2, eFork, 0);

    // shared prep on s2 (input-only deps)
    transw_k<<<144,256,0,s2>>>(w3, wt + 0*WTS);
    transw_k<<<144,256,0,s2>>>(w2, wt + 1*WTS);
    transw_k<<<144,256,0,s2>>>(w1, wt + 2*WTS);
    cudaEventRecord(eWt, s2);
    zpad_k<<<(128*(F2-F) + 255)/256, 256, 0, s2>>>(G);
    cudaEventRecord(eZ, s2);

    const int P = 3*84*84;
    auto chain = [&](cudaStream_t st, int nb, const float* xsrc) {
        packh_k<<<(64*P + 255)/256, 256, 0, st>>>(xsrc, xp + (size_t)nb*P);
        convpool_k<3,1,1,true> <<<dim3(14,8,64),128,0,st>>>(xp, w0, b0, p0, i0, 84, 84, 42, 42, nb);
        convpool16_k<<<dim3(4,4,64),128,smC16,st>>>(p0, w1, b1, p1, i1, 42, 42, 21, 21, nb);
        convpool_k<64,1,1,false><<<dim3(1,8,64),128,0,st>>>(p1, w2, b2, p2, i2, 21, 21, 10, 10, nb);
        convpool_k<64,5,25,true><<<dim3(1,8,13),128,0,st>>>(p2, w3, b3, p3, i3, 10, 10, 5, 5, nb);
        copyp3_k<<<(64*1600 + 255)/256, 256, 0, st>>>(p3, G, scal, nb);
        unpool_fc_k<<<(64*64*100 + 255)/256, 256, 0, st>>>(fcw, cp, i3, d3, nb);
        wgrad2_k<64,8><<<dim3(16,64), 256, sm10, st>>>(d3, nullptr, p2, G, OW3, OB3, scal, 6, 10, 10, 5, 5, nb);
        conv2_k<64,5,25><<<dim3(1,8,13),128,0,st>>>(d3, wt + 0*WTS, dp2, 10, 10, nb);
        wgrad2_k<64,8><<<dim3(16,64), 256, sm21, st>>>(dp2, i2, p1, G, OW2, OB2, scal, 4, 21, 21, 10, 10, nb);
        conv2f_k<8><<<dim3(1,8,64),128, 8*64*12*4, st>>>(dp2, i2, wt + 1*WTS, dp1, 21, 21, 10, 10, nb);
        wgrad2_k<64,8><<<dim3(16,64), 256, sm42, st>>>(dp1, i1, p0, G, OW1, OB1, scal, 2, 42, 42, 21, 21, nb);
        conv2f_k<16><<<dim3(4,4,64),128, smC16, st>>>(dp1, i1, wt + 2*WTS, dp0, 42, 42, 21, 21, nb);
        wgrad0_k<<<dim3(2,64), 256, smW0, st>>>(dp0, i0, xp, G, scal, nb);
    };

    // gate both chains on transposed weights (transw runs first, ~5us)
    cudaStreamWaitEvent(m,  eWt, 0);
    cudaStreamWaitEvent(s1, eWt, 0);
    chain(m,  0,  x1);
    chain(s1, 64, x2);
    cudaEventRecord(eB, s1);

    // join and final GEMM
    cudaStreamWaitEvent(m, eB, 0);
    cudaStreamWaitEvent(m, eZ, 0);
    gemm2_k<<<128, 256, 0, m>>>(G, part);
    reduce_k<<<16, 256, 0, m>>>(part, scal, out);
}